// round 4
// baseline (speedup 1.0000x reference)
#include <cuda_runtime.h>
#include <math.h>

#define NB 4
#define NC 256
#define NN 4096

#define SQ 260     // Q/K smem row stride (floats): banks 4*gid+tig conflict-free
#define SV 264     // V smem row stride: banks 8*tig+gid conflict-free
#define SSTR 68    // S/P and Ot row stride

// scratch: q/k/v stored transposed as (B, N, C), values pre-rounded to tf32
__device__ float g_q[NB*NN*NC];
__device__ float g_k[NB*NN*NC];
__device__ float g_v[NB*NN*NC];

__device__ __forceinline__ void fma4(float4& a, float s, const float4& v) {
    a.x += s * v.x; a.y += s * v.y; a.z += s * v.z; a.w += s * v.w;
}
__device__ __forceinline__ unsigned tf32r(float x) {
    unsigned u; asm("cvt.rna.tf32.f32 %0, %1;" : "=r"(u) : "f"(x)); return u;
}
__device__ __forceinline__ unsigned fbits(float x) { return __float_as_uint(x); }

__device__ __forceinline__ void mma_tf32(float* c, const unsigned* a,
                                         unsigned b0, unsigned b1) {
    asm volatile(
        "mma.sync.aligned.m16n8k8.row.col.f32.tf32.tf32.f32 "
        "{%0,%1,%2,%3}, {%4,%5,%6,%7}, {%8,%9}, {%0,%1,%2,%3};"
        : "+f"(c[0]), "+f"(c[1]), "+f"(c[2]), "+f"(c[3])
        : "r"(a[0]), "r"(a[1]), "r"(a[2]), "r"(a[3]), "r"(b0), "r"(b1));
}

// ---------------------------------------------------------------------------
// QKV projection: dst[b][n][c] = sum_cc W[c][cc] * x[b][cc][n], tf32-rounded.
// ---------------------------------------------------------------------------
__global__ __launch_bounds__(256, 4)
void qkv_proj_kernel(const float* __restrict__ x,
                     const float* __restrict__ Wq,
                     const float* __restrict__ Wk,
                     const float* __restrict__ Wv)
{
    __shared__ float Xs[16][68];
    __shared__ float Ws[16][68];

    const int b = blockIdx.z / 3;
    const int w = blockIdx.z % 3;
    const float* __restrict__ Wm = (w == 0) ? Wq : (w == 1) ? Wk : Wv;
    float* __restrict__ dst      = (w == 0) ? g_q : (w == 1) ? g_k : g_v;

    const int n0 = blockIdx.x * 64;
    const int c0 = blockIdx.y * 64;
    const int t  = threadIdx.x;
    const int ty = t >> 4, tx = t & 15;

    float4 acc[4];
    #pragma unroll
    for (int i = 0; i < 4; i++) acc[i] = make_float4(0.f, 0.f, 0.f, 0.f);

    const int xr = t >> 4, xn = t & 15;
    const int wc = t >> 2, wq = t & 3;

    for (int cc0 = 0; cc0 < NC; cc0 += 16) {
        *(float4*)&Xs[xr][xn * 4] =
            *(const float4*)&x[(b*NC + cc0 + xr)*NN + n0 + xn*4];
        float4 wv = *(const float4*)&Wm[(c0 + wc)*NC + cc0 + wq*4];
        Ws[wq*4 + 0][wc] = wv.x;
        Ws[wq*4 + 1][wc] = wv.y;
        Ws[wq*4 + 2][wc] = wv.z;
        Ws[wq*4 + 3][wc] = wv.w;
        __syncthreads();

        #pragma unroll
        for (int cc = 0; cc < 16; cc++) {
            float4 xv  = *(float4*)&Xs[cc][ty * 4];
            float4 wvv = *(float4*)&Ws[cc][tx * 4];
            fma4(acc[0], xv.x, wvv);
            fma4(acc[1], xv.y, wvv);
            fma4(acc[2], xv.z, wvv);
            fma4(acc[3], xv.w, wvv);
        }
        __syncthreads();
    }

    #pragma unroll
    for (int i = 0; i < 4; i++) {
        acc[i].x = __uint_as_float(tf32r(acc[i].x));
        acc[i].y = __uint_as_float(tf32r(acc[i].y));
        acc[i].z = __uint_as_float(tf32r(acc[i].z));
        acc[i].w = __uint_as_float(tf32r(acc[i].w));
        *(float4*)&dst[(b*NN + n0 + ty*4 + i)*NC + c0 + tx*4] = acc[i];
    }
}

// ---------------------------------------------------------------------------
// Fused flash attention (tf32 mma.sync) + residual epilogue.
// grid (NN/64, NB), 512 threads (16 warps). BM=64 queries, BN=64 keys, d=256.
// S: warp grid 4(row)x4(col), each warp 16x16 of S via m16n8k8 (2 n-tiles).
// PV: computes O^T (d-major); warp w owns d-rows [16w, 16w+16), all 64 queries.
// ---------------------------------------------------------------------------
__global__ __launch_bounds__(512, 1)
void flash_kernel(const float* __restrict__ x,
                  const float* __restrict__ gamma,
                  float* __restrict__ out)
{
    extern __shared__ float sm[];
    float* Qs     = sm;                 // 64*SQ
    float* Ks     = Qs + 64*SQ;         // 64*SQ
    float* Vs     = Ks + 64*SQ;         // 64*SV
    float* Ss     = Vs + 64*SV;         // 64*SSTR
    float* m_row  = Ss + 64*SSTR;       // 64
    float* l_row  = m_row + 64;         // 64
    float* s_scal = l_row + 64;         // 64

    const int b    = blockIdx.y;
    const int n0   = blockIdx.x * 64;
    const int t    = threadIdx.x;
    const int w    = t >> 5;      // 0..15
    const int lane = t & 31;
    const int gid  = lane >> 2;   // 0..7
    const int tig  = lane & 3;    // 0..3
    const int wr   = w >> 2;      // 0..3  (S row-warp)
    const int wcl  = w & 3;       // 0..3  (S col-warp)

    // load Q tile (64 x 256), already tf32-rounded
    for (int i = t; i < 64*64; i += 512) {
        int r = i >> 6, c4 = i & 63;
        *(float4*)(Qs + r*SQ + c4*4) =
            *(const float4*)(g_q + (b*NN + n0 + r)*NC + c4*4);
    }
    if (t < 64) { m_row[t] = -INFINITY; l_row[t] = 0.f; }

    // O^T accum: warp w owns d-rows 16w+{gid, gid+8}; cols (queries) 8nt+2tig+{0,1}
    float o[8][4];
    #pragma unroll
    for (int nt = 0; nt < 8; nt++)
        #pragma unroll
        for (int r = 0; r < 4; r++) o[nt][r] = 0.f;

    const int r0 = 16*wr + gid;   // S-tile row for this thread

    for (int kt = 0; kt < 64; kt++) {
        const int k0g = kt * 64;
        for (int i = t; i < 64*64; i += 512) {
            int r = i >> 6, c4 = i & 63;
            *(float4*)(Ks + r*SQ + c4*4) =
                *(const float4*)(g_k + (b*NN + k0g + r)*NC + c4*4);
            *(float4*)(Vs + r*SV + c4*4) =
                *(const float4*)(g_v + (b*NN + k0g + r)*NC + c4*4);
        }
        __syncthreads();

        // --- S = Q K^T : warp tile 16x16 (2 n-tiles of m16n8k8) ---
        float sacc[2][4];
        #pragma unroll
        for (int j = 0; j < 2; j++)
            #pragma unroll
            for (int r = 0; r < 4; r++) sacc[j][r] = 0.f;

        const float* qb = Qs + r0*SQ;
        const float* kb = Ks + (16*wcl + gid)*SQ;
        #pragma unroll 4
        for (int k0 = 0; k0 < 256; k0 += 8) {
            unsigned a[4];
            a[0] = fbits(qb[k0 + tig]);
            a[1] = fbits(qb[8*SQ + k0 + tig]);
            a[2] = fbits(qb[k0 + tig + 4]);
            a[3] = fbits(qb[8*SQ + k0 + tig + 4]);
            #pragma unroll
            for (int j = 0; j < 2; j++) {
                unsigned b0 = fbits(kb[j*8*SQ + k0 + tig]);
                unsigned b1 = fbits(kb[j*8*SQ + k0 + tig + 4]);
                mma_tf32(sacc[j], a, b0, b1);
            }
        }
        #pragma unroll
        for (int j = 0; j < 2; j++) {
            int c = 16*wcl + 8*j + 2*tig;
            Ss[r0*SSTR + c]       = sacc[j][0];
            Ss[r0*SSTR + c + 1]   = sacc[j][1];
            Ss[(r0+8)*SSTR + c]   = sacc[j][2];
            Ss[(r0+8)*SSTR + c+1] = sacc[j][3];
        }
        __syncthreads();

        // --- online softmax: 8 lanes per row; P stored tf32-rounded ---
        {
            const int r = t >> 3, q = t & 7;
            float* srow = Ss + r*SSTR + q*8;
            float mx = -INFINITY;
            #pragma unroll
            for (int k = 0; k < 8; k++) mx = fmaxf(mx, srow[k]);
            mx = fmaxf(mx, __shfl_xor_sync(0xffffffffu, mx, 1));
            mx = fmaxf(mx, __shfl_xor_sync(0xffffffffu, mx, 2));
            mx = fmaxf(mx, __shfl_xor_sync(0xffffffffu, mx, 4));
            const float m_old = m_row[r];
            const float m_new = fmaxf(m_old, mx);
            float ps = 0.f;
            #pragma unroll
            for (int k = 0; k < 8; k++) {
                float p = __expf(srow[k] - m_new);
                srow[k] = __uint_as_float(tf32r(p));
                ps += p;
            }
            ps += __shfl_xor_sync(0xffffffffu, ps, 1);
            ps += __shfl_xor_sync(0xffffffffu, ps, 2);
            ps += __shfl_xor_sync(0xffffffffu, ps, 4);
            if (q == 0) {
                float corr = __expf(m_old - m_new);
                s_scal[r] = corr;
                l_row[r]  = l_row[r]*corr + ps;
                m_row[r]  = m_new;
            }
        }
        __syncthreads();

        // --- O^T = O^T*corr + V^T P^T ---
        #pragma unroll
        for (int nt = 0; nt < 8; nt++) {
            float s0 = s_scal[8*nt + 2*tig];
            float s1 = s_scal[8*nt + 2*tig + 1];
            o[nt][0] *= s0; o[nt][1] *= s1;
            o[nt][2] *= s0; o[nt][3] *= s1;
        }
        const int m = 16*w + gid;
        #pragma unroll 2
        for (int k0 = 0; k0 < 64; k0 += 8) {
            unsigned av[4];
            av[0] = fbits(Vs[(k0 + tig)*SV + m]);
            av[1] = fbits(Vs[(k0 + tig)*SV + m + 8]);
            av[2] = fbits(Vs[(k0 + tig + 4)*SV + m]);
            av[3] = fbits(Vs[(k0 + tig + 4)*SV + m + 8]);
            #pragma unroll
            for (int nt = 0; nt < 8; nt++) {
                int qn = 8*nt + gid;
                unsigned b0 = fbits(Ss[qn*SSTR + k0 + tig]);
                unsigned b1 = fbits(Ss[qn*SSTR + k0 + tig + 4]);
                mma_tf32(o[nt], av, b0, b1);
            }
        }
        __syncthreads();
    }

    // --- write O^T/l to Ot smem (already channel-major; no transpose) ---
    float* Ot = Qs;  // 256 x SSTR = 17408 floats, fits in Qs+Ks region
    #pragma unroll
    for (int nt = 0; nt < 8; nt++) {
        int q = 8*nt + 2*tig;
        float li0 = __fdividef(1.f, l_row[q]);
        float li1 = __fdividef(1.f, l_row[q + 1]);
        int c = 16*w + gid;
        Ot[c*SSTR + q]         = o[nt][0] * li0;
        Ot[c*SSTR + q + 1]     = o[nt][1] * li1;
        Ot[(c+8)*SSTR + q]     = o[nt][2] * li0;
        Ot[(c+8)*SSTR + q + 1] = o[nt][3] * li1;
    }
    __syncthreads();

    const float g = gamma[0];
    #pragma unroll
    for (int pass = 0; pass < 2; pass++) {
        int c = pass*128 + (t >> 2);
        #pragma unroll
        for (int j = 0; j < 4; j++) {
            int f4 = (t & 3) + j*4;
            float4 ov = *(float4*)(Ot + c*SSTR + f4*4);
            float4 xv = *(const float4*)(x + (b*NC + c)*NN + n0 + f4*4);
            float4 r;
            r.x = g*ov.x + xv.x; r.y = g*ov.y + xv.y;
            r.z = g*ov.z + xv.z; r.w = g*ov.w + xv.w;
            *(float4*)(out + (b*NC + c)*NN + n0 + f4*4) = r;
        }
    }
}

// ---------------------------------------------------------------------------

extern "C" void kernel_launch(void* const* d_in, const int* in_sizes, int n_in,
                              void* d_out, int out_size)
{
    const float* x     = (const float*)d_in[0];
    const float* Wq    = (const float*)d_in[1];
    const float* Wk    = (const float*)d_in[2];
    const float* Wv    = (const float*)d_in[3];
    const float* gamma = (const float*)d_in[4];
    float* out = (float*)d_out;

    const int smem_bytes = (2*64*SQ + 64*SV + 64*SSTR + 3*64) * (int)sizeof(float); // 218880
    cudaFuncSetAttribute(flash_kernel,
                         cudaFuncAttributeMaxDynamicSharedMemorySize, smem_bytes);

    dim3 gp(NN/64, NC/64, 3*NB);
    qkv_proj_kernel<<<gp, 256>>>(x, Wq, Wk, Wv);

    dim3 gf(NN/64, NB);
    flash_kernel<<<gf, 512, smem_bytes>>>(x, gamma, out);
}

// round 9
// speedup vs baseline: 1.6036x; 1.6036x over previous
#include <cuda_runtime.h>
#include <cuda_bf16.h>
#include <cstdint>
#include <math.h>

#define NB 4
#define NC 256
#define NN 4096

// bf16 smem strides (elements)
#define SQK 264    // Q/K rows: 528B = 33 x 16B units -> ldmatrix conflict-free
#define SVP 72     // V^T / P rows: 144B = 9 x 16B units -> conflict-free
#define SSTR 68    // fp32 S staging / Ot stride

// smem byte offsets
#define OFF_Q 0
#define OFF_K 33792
#define OFF_V 67584
#define OFF_P 104448
#define OFF_S 113664
#define OFF_M 131072
#define OFF_L 131328
#define OFF_SC 131584
#define SMEM_BYTES 131840

// scratch: q,k as (B,N,C) bf16; v as (B,C,N) bf16
__device__ __nv_bfloat16 g_q[NB*NN*NC];
__device__ __nv_bfloat16 g_k[NB*NN*NC];
__device__ __nv_bfloat16 g_v[NB*NN*NC];

__device__ __forceinline__ void fma4(float4& a, float s, const float4& v) {
    a.x += s * v.x; a.y += s * v.y; a.z += s * v.z; a.w += s * v.w;
}
__device__ __forceinline__ uint32_t pack2(float a, float b) {
    __nv_bfloat162 h = __floats2bfloat162_rn(a, b);
    return *(uint32_t*)&h;
}
__device__ __forceinline__ uint32_t smem_u32(const void* p) {
    uint32_t a;
    asm("{ .reg .u64 t; cvta.to.shared.u64 t, %1; cvt.u32.u64 %0, t; }" : "=r"(a) : "l"(p));
    return a;
}
__device__ __forceinline__ void ldsm4(uint32_t& r0, uint32_t& r1, uint32_t& r2,
                                      uint32_t& r3, uint32_t addr) {
    asm volatile("ldmatrix.sync.aligned.m8n8.x4.shared.b16 {%0,%1,%2,%3}, [%4];"
                 : "=r"(r0), "=r"(r1), "=r"(r2), "=r"(r3) : "r"(addr));
}
__device__ __forceinline__ void mma_bf16(float* c, const uint32_t* a,
                                         uint32_t b0, uint32_t b1) {
    asm volatile(
        "mma.sync.aligned.m16n8k16.row.col.f32.bf16.bf16.f32 "
        "{%0,%1,%2,%3}, {%4,%5,%6,%7}, {%8,%9}, {%0,%1,%2,%3};"
        : "+f"(c[0]), "+f"(c[1]), "+f"(c[2]), "+f"(c[3])
        : "r"(a[0]), "r"(a[1]), "r"(a[2]), "r"(a[3]), "r"(b0), "r"(b1));
}

// ---------------------------------------------------------------------------
// QKV projection: q,k -> (B,N,C) bf16; v -> (B,C,N) bf16.
// ---------------------------------------------------------------------------
__global__ __launch_bounds__(256, 4)
void qkv_proj_kernel(const float* __restrict__ x,
                     const float* __restrict__ Wq,
                     const float* __restrict__ Wk,
                     const float* __restrict__ Wv)
{
    __shared__ float Xs[16][68];
    __shared__ float Ws[16][68];

    const int b = blockIdx.z / 3;
    const int w = blockIdx.z % 3;
    const float* __restrict__ Wm = (w == 0) ? Wq : (w == 1) ? Wk : Wv;
    __nv_bfloat16* __restrict__ dst = (w == 0) ? g_q : (w == 1) ? g_k : g_v;

    const int n0 = blockIdx.x * 64;
    const int c0 = blockIdx.y * 64;
    const int t  = threadIdx.x;
    const int ty = t >> 4, tx = t & 15;

    float4 acc[4];
    #pragma unroll
    for (int i = 0; i < 4; i++) acc[i] = make_float4(0.f, 0.f, 0.f, 0.f);

    const int xr = t >> 4, xn = t & 15;
    const int wc = t >> 2, wq = t & 3;

    for (int cc0 = 0; cc0 < NC; cc0 += 16) {
        *(float4*)&Xs[xr][xn * 4] =
            *(const float4*)&x[(b*NC + cc0 + xr)*NN + n0 + xn*4];
        float4 wv = *(const float4*)&Wm[(c0 + wc)*NC + cc0 + wq*4];
        Ws[wq*4 + 0][wc] = wv.x;
        Ws[wq*4 + 1][wc] = wv.y;
        Ws[wq*4 + 2][wc] = wv.z;
        Ws[wq*4 + 3][wc] = wv.w;
        __syncthreads();

        #pragma unroll
        for (int cc = 0; cc < 16; cc++) {
            float4 xv  = *(float4*)&Xs[cc][ty * 4];
            float4 wvv = *(float4*)&Ws[cc][tx * 4];
            fma4(acc[0], xv.x, wvv);
            fma4(acc[1], xv.y, wvv);
            fma4(acc[2], xv.z, wvv);
            fma4(acc[3], xv.w, wvv);
        }
        __syncthreads();
    }

    if (w == 2) {
        // v: (B,C,N) — transpose 4x4 block, pack pairs along N
        float* a = (float*)acc;  // a[i*4 + j]
        #pragma unroll
        for (int j = 0; j < 4; j++) {
            uint2 pv;
            pv.x = pack2(a[0*4 + j], a[1*4 + j]);
            pv.y = pack2(a[2*4 + j], a[3*4 + j]);
            *(uint2*)&dst[(size_t)(b*NC + c0 + tx*4 + j)*NN + n0 + ty*4] = pv;
        }
    } else {
        #pragma unroll
        for (int i = 0; i < 4; i++) {
            uint2 pv;
            pv.x = pack2(acc[i].x, acc[i].y);
            pv.y = pack2(acc[i].z, acc[i].w);
            *(uint2*)&dst[(size_t)(b*NN + n0 + ty*4 + i)*NC + c0 + tx*4] = pv;
        }
    }
}

// ---------------------------------------------------------------------------
// Fused flash attention (bf16 mma.sync m16n8k16 + ldmatrix) + residual.
// grid (NN/64, NB), 512 threads (16 warps). BM=64, BN=64, d=256.
// S: warp grid 4x4, each warp 16x16 (2 n-tiles). PV: warp w owns d-rows
// [16w,16w+16), computes O^T. Online softmax, P stored bf16.
// ---------------------------------------------------------------------------
__global__ __launch_bounds__(512, 1)
void flash_kernel(const float* __restrict__ x,
                  const float* __restrict__ gamma,
                  float* __restrict__ out)
{
    extern __shared__ char smem[];
    const uint32_t sb = smem_u32(smem);
    float* Ss     = (float*)(smem + OFF_S);
    float* m_row  = (float*)(smem + OFF_M);
    float* l_row  = (float*)(smem + OFF_L);
    float* s_scal = (float*)(smem + OFF_SC);

    const int b    = blockIdx.y;
    const int n0   = blockIdx.x * 64;
    const int t    = threadIdx.x;
    const int w    = t >> 5;
    const int lane = t & 31;
    const int gid  = lane >> 2;
    const int tig  = lane & 3;
    const int wr   = w >> 2;
    const int wcl  = w & 3;

    // ldmatrix per-lane addressing: row = base + (lane&15), kofs = (lane>>4)*8
    const int lrow = lane & 15;
    const int lk   = (lane >> 4) * 8;

    // load Q tile: 64 rows x 256 bf16 (rows contiguous in gmem)
    {
        const uint4* qg = (const uint4*)(g_q + (size_t)(b*NN + n0)*NC);
        #pragma unroll
        for (int it = 0; it < 4; it++) {
            int i = t + it*512;
            int r = i >> 5, gq = i & 31;
            *(uint4*)(smem + OFF_Q + r*(SQK*2) + gq*16) = qg[i];
        }
    }
    if (t < 64) { m_row[t] = -INFINITY; l_row[t] = 0.f; }

    float o[8][4];
    #pragma unroll
    for (int nt = 0; nt < 8; nt++)
        #pragma unroll
        for (int r = 0; r < 4; r++) o[nt][r] = 0.f;

    const uint32_t qa_base = sb + OFF_Q + ((16*wr  + lrow)*SQK + lk)*2;
    const uint32_t ka_base = sb + OFF_K + ((16*wcl + lrow)*SQK + lk)*2;
    const uint32_t va_base = sb + OFF_V + ((16*w   + lrow)*SVP + lk)*2;
    uint32_t pa_base[4];
    #pragma unroll
    for (int jq = 0; jq < 4; jq++)
        pa_base[jq] = sb + OFF_P + ((16*jq + lrow)*SVP + lk)*2;

    const int r0 = 16*wr + gid;   // S row for this thread

    for (int kt = 0; kt < 64; kt++) {
        const int k0g = kt * 64;
        // K tile (rows contiguous), V tile (channel rows, strided)
        {
            const uint4* kg = (const uint4*)(g_k + (size_t)(b*NN + k0g)*NC);
            #pragma unroll
            for (int it = 0; it < 4; it++) {
                int i = t + it*512;
                int r = i >> 5, gq = i & 31;
                *(uint4*)(smem + OFF_K + r*(SQK*2) + gq*16) = kg[i];
            }
            const __nv_bfloat16* vgb = g_v + (size_t)b*NC*NN + k0g;
            #pragma unroll
            for (int it = 0; it < 4; it++) {
                int i = t + it*512;
                int c = i >> 3, u = i & 7;
                *(uint4*)(smem + OFF_V + c*(SVP*2) + u*16) =
                    ((const uint4*)(vgb + (size_t)c*NN))[u];
            }
        }
        __syncthreads();

        // --- S = Q K^T : warp tile 16x16, 16 k-steps of k=16 ---
        float sacc[2][4];
        #pragma unroll
        for (int j = 0; j < 2; j++)
            #pragma unroll
            for (int r = 0; r < 4; r++) sacc[j][r] = 0.f;

        #pragma unroll
        for (int s = 0; s < 16; s++) {
            uint32_t a[4], b0, b1, b2, b3;
            ldsm4(a[0], a[1], a[2], a[3], qa_base + 32*s);
            ldsm4(b0, b1, b2, b3, ka_base + 32*s);
            mma_bf16(sacc[0], a, b0, b2);
            mma_bf16(sacc[1], a, b1, b3);
        }
        #pragma unroll
        for (int j = 0; j < 2; j++) {
            int c = 16*wcl + 8*j + 2*tig;
            Ss[r0*SSTR + c]       = sacc[j][0];
            Ss[r0*SSTR + c + 1]   = sacc[j][1];
            Ss[(r0+8)*SSTR + c]   = sacc[j][2];
            Ss[(r0+8)*SSTR + c+1] = sacc[j][3];
        }
        __syncthreads();

        // --- online softmax: 8 lanes/row; P written packed bf16 ---
        {
            const int r = t >> 3, q = t & 7;
            const float* srow = Ss + r*SSTR + q*8;
            float sv[8];
            #pragma unroll
            for (int k = 0; k < 8; k++) sv[k] = srow[k];
            float mx = sv[0];
            #pragma unroll
            for (int k = 1; k < 8; k++) mx = fmaxf(mx, sv[k]);
            mx = fmaxf(mx, __shfl_xor_sync(0xffffffffu, mx, 1));
            mx = fmaxf(mx, __shfl_xor_sync(0xffffffffu, mx, 2));
            mx = fmaxf(mx, __shfl_xor_sync(0xffffffffu, mx, 4));
            const float m_old = m_row[r];
            const float m_new = fmaxf(m_old, mx);
            float p[8];
            float ps = 0.f;
            #pragma unroll
            for (int k = 0; k < 8; k++) {
                p[k] = __expf(sv[k] - m_new);
                ps += p[k];
            }
            uint4 pw;
            pw.x = pack2(p[0], p[1]);
            pw.y = pack2(p[2], p[3]);
            pw.z = pack2(p[4], p[5]);
            pw.w = pack2(p[6], p[7]);
            *(uint4*)(smem + OFF_P + r*(SVP*2) + q*16) = pw;
            ps += __shfl_xor_sync(0xffffffffu, ps, 1);
            ps += __shfl_xor_sync(0xffffffffu, ps, 2);
            ps += __shfl_xor_sync(0xffffffffu, ps, 4);
            if (q == 0) {
                float corr = __expf(m_old - m_new);
                s_scal[r] = corr;
                l_row[r]  = l_row[r]*corr + ps;
                m_row[r]  = m_new;
            }
        }
        __syncthreads();

        // --- O^T = O^T*corr + V^T P^T : 4 k-steps of 16 keys ---
        #pragma unroll
        for (int nt = 0; nt < 8; nt++) {
            float s0 = s_scal[8*nt + 2*tig];
            float s1 = s_scal[8*nt + 2*tig + 1];
            o[nt][0] *= s0; o[nt][1] *= s1;
            o[nt][2] *= s0; o[nt][3] *= s1;
        }
        #pragma unroll
        for (int s = 0; s < 4; s++) {
            uint32_t av[4];
            ldsm4(av[0], av[1], av[2], av[3], va_base + 32*s);
            #pragma unroll
            for (int jq = 0; jq < 4; jq++) {
                uint32_t p0, p1, p2, p3;
                ldsm4(p0, p1, p2, p3, pa_base[jq] + 32*s);
                mma_bf16(o[2*jq],     av, p0, p2);
                mma_bf16(o[2*jq + 1], av, p1, p3);
            }
        }
        __syncthreads();
    }

    // --- write O^T/l to Ot smem (channel-major already) ---
    float* Ot = (float*)(smem + OFF_Q);  // 256*68*4 = 69632 <= OFF_P
    #pragma unroll
    for (int nt = 0; nt < 8; nt++) {
        int q = 8*nt + 2*tig;
        float li0 = __fdividef(1.f, l_row[q]);
        float li1 = __fdividef(1.f, l_row[q + 1]);
        int c = 16*w + gid;
        Ot[c*SSTR + q]         = o[nt][0] * li0;
        Ot[c*SSTR + q + 1]     = o[nt][1] * li1;
        Ot[(c+8)*SSTR + q]     = o[nt][2] * li0;
        Ot[(c+8)*SSTR + q + 1] = o[nt][3] * li1;
    }
    __syncthreads();

    const float g = gamma[0];
    #pragma unroll
    for (int pass = 0; pass < 2; pass++) {
        int c = pass*128 + (t >> 2);
        #pragma unroll
        for (int j = 0; j < 4; j++) {
            int f4 = (t & 3) + j*4;
            float4 ov = *(float4*)(Ot + c*SSTR + f4*4);
            float4 xv = *(const float4*)(x + (size_t)(b*NC + c)*NN + n0 + f4*4);
            float4 r;
            r.x = g*ov.x + xv.x; r.y = g*ov.y + xv.y;
            r.z = g*ov.z + xv.z; r.w = g*ov.w + xv.w;
            *(float4*)(out + (size_t)(b*NC + c)*NN + n0 + f4*4) = r;
        }
    }
}

// ---------------------------------------------------------------------------

extern "C" void kernel_launch(void* const* d_in, const int* in_sizes, int n_in,
                              void* d_out, int out_size)
{
    const float* x     = (const float*)d_in[0];
    const float* Wq    = (const float*)d_in[1];
    const float* Wk    = (const float*)d_in[2];
    const float* Wv    = (const float*)d_in[3];
    const float* gamma = (const float*)d_in[4];
    float* out = (float*)d_out;

    cudaFuncSetAttribute(flash_kernel,
                         cudaFuncAttributeMaxDynamicSharedMemorySize, SMEM_BYTES);

    dim3 gp(NN/64, NC/64, 3*NB);
    qkv_proj_kernel<<<gp, 256>>>(x, Wq, Wk, Wv);

    dim3 gf(NN/64, NB);
    flash_kernel<<<gf, 512, SMEM_BYTES>>>(x, gamma, out);
}

// round 10
// speedup vs baseline: 1.8654x; 1.1633x over previous
#include <cuda_runtime.h>
#include <cuda_fp16.h>
#include <cstdint>
#include <math.h>

#define NB 4
#define NC 256
#define NN 4096

// fp16 smem strides (elements)
#define SQK 264    // Q/K rows: 528B -> ldmatrix conflict-free
#define SVP 72     // V / P rows: 144B -> conflict-free
#define SSTR 68    // fp32 Ot stride

// smem byte offsets
#define OFF_Q    0
#define OFF_K    33792
#define OFF_V    67584
#define OFF_P    104448
#define OFF_PMAX 113664
#define OFF_PSUM 114176
#define OFF_SCAL 114688
#define OFF_LROW 114944
#define SMEM_BYTES 115200

// scratch: q,k as (B,N,C) fp16; v as (B,C,N) fp16
__device__ __half g_q[NB*NN*NC];
__device__ __half g_k[NB*NN*NC];
__device__ __half g_v[NB*NN*NC];

__device__ __forceinline__ void fma4(float4& a, float s, const float4& v) {
    a.x += s * v.x; a.y += s * v.y; a.z += s * v.z; a.w += s * v.w;
}
__device__ __forceinline__ uint32_t pack2(float a, float b) {
    __half2 h = __floats2half2_rn(a, b);
    return *(uint32_t*)&h;
}
__device__ __forceinline__ uint32_t smem_u32(const void* p) {
    uint32_t a;
    asm("{ .reg .u64 t; cvta.to.shared.u64 t, %1; cvt.u32.u64 %0, t; }" : "=r"(a) : "l"(p));
    return a;
}
__device__ __forceinline__ void ldsm4(uint32_t& r0, uint32_t& r1, uint32_t& r2,
                                      uint32_t& r3, uint32_t addr) {
    asm volatile("ldmatrix.sync.aligned.m8n8.x4.shared.b16 {%0,%1,%2,%3}, [%4];"
                 : "=r"(r0), "=r"(r1), "=r"(r2), "=r"(r3) : "r"(addr));
}
__device__ __forceinline__ void mma_f16(float* c, const uint32_t* a,
                                        uint32_t b0, uint32_t b1) {
    asm volatile(
        "mma.sync.aligned.m16n8k16.row.col.f32.f16.f16.f32 "
        "{%0,%1,%2,%3}, {%4,%5,%6,%7}, {%8,%9}, {%0,%1,%2,%3};"
        : "+f"(c[0]), "+f"(c[1]), "+f"(c[2]), "+f"(c[3])
        : "r"(a[0]), "r"(a[1]), "r"(a[2]), "r"(a[3]), "r"(b0), "r"(b1));
}

// ---------------------------------------------------------------------------
// QKV projection: q,k -> (B,N,C) fp16; v -> (B,C,N) fp16.
// ---------------------------------------------------------------------------
__global__ __launch_bounds__(256, 4)
void qkv_proj_kernel(const float* __restrict__ x,
                     const float* __restrict__ Wq,
                     const float* __restrict__ Wk,
                     const float* __restrict__ Wv)
{
    __shared__ float Xs[16][68];
    __shared__ float Ws[16][68];

    const int b = blockIdx.z / 3;
    const int w = blockIdx.z % 3;
    const float* __restrict__ Wm = (w == 0) ? Wq : (w == 1) ? Wk : Wv;
    __half* __restrict__ dst = (w == 0) ? g_q : (w == 1) ? g_k : g_v;

    const int n0 = blockIdx.x * 64;
    const int c0 = blockIdx.y * 64;
    const int t  = threadIdx.x;
    const int ty = t >> 4, tx = t & 15;

    float4 acc[4];
    #pragma unroll
    for (int i = 0; i < 4; i++) acc[i] = make_float4(0.f, 0.f, 0.f, 0.f);

    const int xr = t >> 4, xn = t & 15;
    const int wc = t >> 2, wq = t & 3;

    for (int cc0 = 0; cc0 < NC; cc0 += 16) {
        *(float4*)&Xs[xr][xn * 4] =
            *(const float4*)&x[(b*NC + cc0 + xr)*NN + n0 + xn*4];
        float4 wv = *(const float4*)&Wm[(c0 + wc)*NC + cc0 + wq*4];
        Ws[wq*4 + 0][wc] = wv.x;
        Ws[wq*4 + 1][wc] = wv.y;
        Ws[wq*4 + 2][wc] = wv.z;
        Ws[wq*4 + 3][wc] = wv.w;
        __syncthreads();

        #pragma unroll
        for (int cc = 0; cc < 16; cc++) {
            float4 xv  = *(float4*)&Xs[cc][ty * 4];
            float4 wvv = *(float4*)&Ws[cc][tx * 4];
            fma4(acc[0], xv.x, wvv);
            fma4(acc[1], xv.y, wvv);
            fma4(acc[2], xv.z, wvv);
            fma4(acc[3], xv.w, wvv);
        }
        __syncthreads();
    }

    if (w == 2) {
        float* a = (float*)acc;  // a[i*4 + j]
        #pragma unroll
        for (int j = 0; j < 4; j++) {
            uint2 pv;
            pv.x = pack2(a[0*4 + j], a[1*4 + j]);
            pv.y = pack2(a[2*4 + j], a[3*4 + j]);
            *(uint2*)&dst[(size_t)(b*NC + c0 + tx*4 + j)*NN + n0 + ty*4] = pv;
        }
    } else {
        #pragma unroll
        for (int i = 0; i < 4; i++) {
            uint2 pv;
            pv.x = pack2(acc[i].x, acc[i].y);
            pv.y = pack2(acc[i].z, acc[i].w);
            *(uint2*)&dst[(size_t)(b*NN + n0 + ty*4 + i)*NC + c0 + tx*4] = pv;
        }
    }
}

// ---------------------------------------------------------------------------
// Fused flash attention (fp16 mma.sync, Q hoisted in regs, reg softmax).
// grid (NN/64, NB), 256 threads (8 warps). BM=64, BN=64, d=256.
// S: warp grid 4(wr)x2(wcl), warp tile 16x32.
// PV: warp w owns d-rows [32w, 32w+32), computes O^T (all 64 queries).
// ---------------------------------------------------------------------------
__global__ __launch_bounds__(256, 1)
void flash_kernel(const float* __restrict__ x,
                  const float* __restrict__ gamma,
                  float* __restrict__ out)
{
    extern __shared__ char smem[];
    const uint32_t sb = smem_u32(smem);
    float* pmax   = (float*)(smem + OFF_PMAX);   // [2][64]
    float* psum   = (float*)(smem + OFF_PSUM);   // [2][64]
    float* s_scal = (float*)(smem + OFF_SCAL);   // [64]
    float* l_row  = (float*)(smem + OFF_LROW);   // [64]

    const int b    = blockIdx.y;
    const int n0   = blockIdx.x * 64;
    const int t    = threadIdx.x;
    const int w    = t >> 5;      // 0..7
    const int lane = t & 31;
    const int gid  = lane >> 2;   // 0..7
    const int tig  = lane & 3;    // 0..3
    const int wr   = w >> 1;      // 0..3
    const int wcl  = w & 1;       // 0..1
    const int lrow = lane & 15;
    const int lk   = (lane >> 4) * 8;

    // load Q tile (64 x 256 fp16) to smem
    {
        const uint4* qg = (const uint4*)(g_q + (size_t)(b*NN + n0)*NC);
        #pragma unroll
        for (int it = 0; it < 8; it++) {
            int i = t + it*256;
            int r = i >> 5, gq = i & 31;
            *(uint4*)(smem + OFF_Q + r*(SQK*2) + gq*16) = qg[i];
        }
    }
    __syncthreads();

    // hoist Q fragments: rows 16*wr..+16, all 256 d (16 k-steps)
    uint32_t qf[16][4];
    {
        const uint32_t qa = sb + OFF_Q + ((16*wr + lrow)*SQK + lk)*2;
        #pragma unroll
        for (int s = 0; s < 16; s++)
            ldsm4(qf[s][0], qf[s][1], qf[s][2], qf[s][3], qa + 32*s);
    }

    const int r0 = 16*wr + gid;          // S rows r0, r0+8
    float m_prev[2] = {-INFINITY, -INFINITY};
    float l_acc[2]  = {0.f, 0.f};

    float o[2][8][4];  // [mt][nt][r]: d-row 32w+16mt+gid(+8), query 8nt+2tig+(r&1)
    #pragma unroll
    for (int mt = 0; mt < 2; mt++)
        #pragma unroll
        for (int nt = 0; nt < 8; nt++)
            #pragma unroll
            for (int r = 0; r < 4; r++) o[mt][nt][r] = 0.f;

    const uint32_t ka_base = sb + OFF_K + ((32*wcl + lrow)*SQK + lk)*2;
    const uint32_t va_base = sb + OFF_V + ((32*w + lrow)*SVP + lk)*2;
    uint32_t pa_base[4];
    #pragma unroll
    for (int jq = 0; jq < 4; jq++)
        pa_base[jq] = sb + OFF_P + ((16*jq + lrow)*SVP + lk)*2;

    for (int kt = 0; kt < 64; kt++) {
        const int k0g = kt * 64;
        // --- load K (rows contig), V (channel rows) tiles ---
        {
            const uint4* kg = (const uint4*)(g_k + (size_t)(b*NN + k0g)*NC);
            #pragma unroll
            for (int it = 0; it < 8; it++) {
                int i = t + it*256;
                int r = i >> 5, gq = i & 31;
                *(uint4*)(smem + OFF_K + r*(SQK*2) + gq*16) = kg[i];
            }
            const __half* vgb = g_v + (size_t)b*NC*NN + k0g;
            #pragma unroll
            for (int it = 0; it < 8; it++) {
                int i = t + it*256;
                int c = i >> 3, u = i & 7;
                *(uint4*)(smem + OFF_V + c*(SVP*2) + u*16) =
                    ((const uint4*)(vgb + (size_t)c*NN))[u];
            }
        }
        __syncthreads();   // bar1: K/V ready

        // --- S = Q K^T : warp tile 16x32 (4 n-tiles) ---
        float sacc[4][4];
        #pragma unroll
        for (int j = 0; j < 4; j++)
            #pragma unroll
            for (int r = 0; r < 4; r++) sacc[j][r] = 0.f;

        #pragma unroll
        for (int s = 0; s < 16; s++) {
            uint32_t b0, b1, b2, b3, c0, c1, c2, c3;
            ldsm4(b0, b1, b2, b3, ka_base + 32*s);
            ldsm4(c0, c1, c2, c3, ka_base + 16*(SQK*2) + 32*s);
            mma_f16(sacc[0], qf[s], b0, b2);
            mma_f16(sacc[1], qf[s], b1, b3);
            mma_f16(sacc[2], qf[s], c0, c2);
            mma_f16(sacc[3], qf[s], c1, c3);
        }

        // warp-partial row max over this warp's 32 cols
        {
            float mx0 = fmaxf(fmaxf(sacc[0][0], sacc[0][1]), fmaxf(sacc[1][0], sacc[1][1]));
            mx0 = fmaxf(mx0, fmaxf(fmaxf(sacc[2][0], sacc[2][1]), fmaxf(sacc[3][0], sacc[3][1])));
            float mx1 = fmaxf(fmaxf(sacc[0][2], sacc[0][3]), fmaxf(sacc[1][2], sacc[1][3]));
            mx1 = fmaxf(mx1, fmaxf(fmaxf(sacc[2][2], sacc[2][3]), fmaxf(sacc[3][2], sacc[3][3])));
            mx0 = fmaxf(mx0, __shfl_xor_sync(0xffffffffu, mx0, 1));
            mx0 = fmaxf(mx0, __shfl_xor_sync(0xffffffffu, mx0, 2));
            mx1 = fmaxf(mx1, __shfl_xor_sync(0xffffffffu, mx1, 1));
            mx1 = fmaxf(mx1, __shfl_xor_sync(0xffffffffu, mx1, 2));
            if (tig == 0) {
                pmax[wcl*64 + r0]     = mx0;
                pmax[wcl*64 + r0 + 8] = mx1;
            }
        }
        __syncthreads();   // bar2: partial maxima ready

        // --- softmax in registers ---
        float corr0, corr1;
        {
            float m_new0 = fmaxf(m_prev[0], fmaxf(pmax[r0],     pmax[64 + r0]));
            float m_new1 = fmaxf(m_prev[1], fmaxf(pmax[r0 + 8], pmax[64 + r0 + 8]));
            corr0 = __expf(m_prev[0] - m_new0);
            corr1 = __expf(m_prev[1] - m_new1);
            m_prev[0] = m_new0; m_prev[1] = m_new1;

            float ps0 = 0.f, ps1 = 0.f;
            #pragma unroll
            for (int j = 0; j < 4; j++) {
                float p0 = __expf(sacc[j][0] - m_new0);
                float p1 = __expf(sacc[j][1] - m_new0);
                float p2 = __expf(sacc[j][2] - m_new1);
                float p3 = __expf(sacc[j][3] - m_new1);
                ps0 += p0 + p1; ps1 += p2 + p3;
                int cj = 32*wcl + 8*j + 2*tig;
                *(uint32_t*)(smem + OFF_P + (r0*SVP + cj)*2)       = pack2(p0, p1);
                *(uint32_t*)(smem + OFF_P + ((r0 + 8)*SVP + cj)*2) = pack2(p2, p3);
            }
            ps0 += __shfl_xor_sync(0xffffffffu, ps0, 1);
            ps0 += __shfl_xor_sync(0xffffffffu, ps0, 2);
            ps1 += __shfl_xor_sync(0xffffffffu, ps1, 1);
            ps1 += __shfl_xor_sync(0xffffffffu, ps1, 2);
            if (tig == 0) {
                psum[wcl*64 + r0]     = ps0;
                psum[wcl*64 + r0 + 8] = ps1;
            }
            if (wcl == 0 && tig == 0) {
                s_scal[r0]     = corr0;
                s_scal[r0 + 8] = corr1;
            }
        }
        __syncthreads();   // bar3: P / psum / s_scal ready

        l_acc[0] = l_acc[0]*corr0 + psum[r0]     + psum[64 + r0];
        l_acc[1] = l_acc[1]*corr1 + psum[r0 + 8] + psum[64 + r0 + 8];

        // --- O^T = O^T*corr + V^T P^T ---
        #pragma unroll
        for (int nt = 0; nt < 8; nt++) {
            float s0 = s_scal[8*nt + 2*tig];
            float s1 = s_scal[8*nt + 2*tig + 1];
            #pragma unroll
            for (int mt = 0; mt < 2; mt++) {
                o[mt][nt][0] *= s0; o[mt][nt][1] *= s1;
                o[mt][nt][2] *= s0; o[mt][nt][3] *= s1;
            }
        }
        #pragma unroll
        for (int s = 0; s < 4; s++) {
            uint32_t av0[4], av1[4];
            ldsm4(av0[0], av0[1], av0[2], av0[3], va_base + 32*s);
            ldsm4(av1[0], av1[1], av1[2], av1[3], va_base + 16*(SVP*2) + 32*s);
            #pragma unroll
            for (int jq = 0; jq < 4; jq++) {
                uint32_t p0, p1, p2, p3;
                ldsm4(p0, p1, p2, p3, pa_base[jq] + 32*s);
                mma_f16(o[0][2*jq],     av0, p0, p2);
                mma_f16(o[0][2*jq + 1], av0, p1, p3);
                mma_f16(o[1][2*jq],     av1, p0, p2);
                mma_f16(o[1][2*jq + 1], av1, p1, p3);
            }
        }
        __syncthreads();   // bar4: V/P consumed, safe to overwrite
    }

    if (wcl == 0 && tig == 0) {
        l_row[r0]     = l_acc[0];
        l_row[r0 + 8] = l_acc[1];
    }
    __syncthreads();

    // --- O^T/l to Ot smem (channel-major already) ---
    float* Ot = (float*)(smem + OFF_Q);  // 256*68*4 = 69632 < OFF_P
    #pragma unroll
    for (int nt = 0; nt < 8; nt++) {
        int q = 8*nt + 2*tig;
        float li0 = __fdividef(1.f, l_row[q]);
        float li1 = __fdividef(1.f, l_row[q + 1]);
        #pragma unroll
        for (int mt = 0; mt < 2; mt++) {
            int c = 32*w + 16*mt + gid;
            Ot[c*SSTR + q]         = o[mt][nt][0] * li0;
            Ot[c*SSTR + q + 1]     = o[mt][nt][1] * li1;
            Ot[(c+8)*SSTR + q]     = o[mt][nt][2] * li0;
            Ot[(c+8)*SSTR + q + 1] = o[mt][nt][3] * li1;
        }
    }
    __syncthreads();

    const float g = gamma[0];
    #pragma unroll
    for (int pass = 0; pass < 4; pass++) {
        int c = pass*64 + (t >> 2);
        #pragma unroll
        for (int j = 0; j < 4; j++) {
            int f4 = (t & 3) + j*4;
            float4 ov = *(float4*)(Ot + c*SSTR + f4*4);
            float4 xv = *(const float4*)(x + (size_t)(b*NC + c)*NN + n0 + f4*4);
            float4 r;
            r.x = g*ov.x + xv.x; r.y = g*ov.y + xv.y;
            r.z = g*ov.z + xv.z; r.w = g*ov.w + xv.w;
            *(float4*)(out + (size_t)(b*NC + c)*NN + n0 + f4*4) = r;
        }
    }
}

// ---------------------------------------------------------------------------

extern "C" void kernel_launch(void* const* d_in, const int* in_sizes, int n_in,
                              void* d_out, int out_size)
{
    const float* x     = (const float*)d_in[0];
    const float* Wq    = (const float*)d_in[1];
    const float* Wk    = (const float*)d_in[2];
    const float* Wv    = (const float*)d_in[3];
    const float* gamma = (const float*)d_in[4];
    float* out = (float*)d_out;

    cudaFuncSetAttribute(flash_kernel,
                         cudaFuncAttributeMaxDynamicSharedMemorySize, SMEM_BYTES);

    dim3 gp(NN/64, NC/64, 3*NB);
    qkv_proj_kernel<<<gp, 256>>>(x, Wq, Wk, Wv);

    dim3 gf(NN/64, NB);
    flash_kernel<<<gf, 256, SMEM_BYTES>>>(x, gamma, out);
}

// round 11
// speedup vs baseline: 1.9940x; 1.0689x over previous
#include <cuda_runtime.h>
#include <cuda_fp16.h>
#include <cstdint>
#include <math.h>

#define NB 4
#define NC 256
#define NN 4096

// fp16 smem strides (elements)
#define SQK 264    // Q/K rows: 528B -> ldmatrix conflict-free
#define SVP 72     // V / P rows: 144B -> conflict-free
#define SSTR 68    // fp32 Ot stride

// smem byte offsets (K/V are 2-stage ring buffers)
#define OFF_Q    0
#define OFF_K    33792
#define KSTAGE   33792
#define OFF_V    101376
#define VSTAGE   36864
#define OFF_P    175104
#define OFF_PMAX 184320
#define OFF_PSUM 184832
#define OFF_SCAL 185344
#define OFF_LROW 185600
#define SMEM_BYTES 185856

// scratch: q,k as (B,N,C) fp16; v as (B,C,N) fp16
__device__ __half g_q[NB*NN*NC];
__device__ __half g_k[NB*NN*NC];
__device__ __half g_v[NB*NN*NC];

__device__ __forceinline__ void fma4(float4& a, float s, const float4& v) {
    a.x += s * v.x; a.y += s * v.y; a.z += s * v.z; a.w += s * v.w;
}
__device__ __forceinline__ uint32_t pack2(float a, float b) {
    __half2 h = __floats2half2_rn(a, b);
    return *(uint32_t*)&h;
}
__device__ __forceinline__ uint32_t smem_u32(const void* p) {
    uint32_t a;
    asm("{ .reg .u64 t; cvta.to.shared.u64 t, %1; cvt.u32.u64 %0, t; }" : "=r"(a) : "l"(p));
    return a;
}
__device__ __forceinline__ void ldsm4(uint32_t& r0, uint32_t& r1, uint32_t& r2,
                                      uint32_t& r3, uint32_t addr) {
    asm volatile("ldmatrix.sync.aligned.m8n8.x4.shared.b16 {%0,%1,%2,%3}, [%4];"
                 : "=r"(r0), "=r"(r1), "=r"(r2), "=r"(r3) : "r"(addr));
}
__device__ __forceinline__ void mma_f16(float* c, const uint32_t* a,
                                        uint32_t b0, uint32_t b1) {
    asm volatile(
        "mma.sync.aligned.m16n8k16.row.col.f32.f16.f16.f32 "
        "{%0,%1,%2,%3}, {%4,%5,%6,%7}, {%8,%9}, {%0,%1,%2,%3};"
        : "+f"(c[0]), "+f"(c[1]), "+f"(c[2]), "+f"(c[3])
        : "r"(a[0]), "r"(a[1]), "r"(a[2]), "r"(a[3]), "r"(b0), "r"(b1));
}
__device__ __forceinline__ void cp16(uint32_t saddr, const void* gaddr) {
    asm volatile("cp.async.cg.shared.global [%0], [%1], 16;"
                 :: "r"(saddr), "l"(gaddr));
}
#define CP_COMMIT()   asm volatile("cp.async.commit_group;" ::: "memory")
#define CP_WAIT(n)    asm volatile("cp.async.wait_group %0;" :: "n"(n) : "memory")

// ---------------------------------------------------------------------------
// QKV projection: q,k -> (B,N,C) fp16; v -> (B,C,N) fp16.
// ---------------------------------------------------------------------------
__global__ __launch_bounds__(256, 4)
void qkv_proj_kernel(const float* __restrict__ x,
                     const float* __restrict__ Wq,
                     const float* __restrict__ Wk,
                     const float* __restrict__ Wv)
{
    __shared__ float Xs[16][68];
    __shared__ float Ws[16][68];

    const int b = blockIdx.z / 3;
    const int w = blockIdx.z % 3;
    const float* __restrict__ Wm = (w == 0) ? Wq : (w == 1) ? Wk : Wv;
    __half* __restrict__ dst = (w == 0) ? g_q : (w == 1) ? g_k : g_v;

    const int n0 = blockIdx.x * 64;
    const int c0 = blockIdx.y * 64;
    const int t  = threadIdx.x;
    const int ty = t >> 4, tx = t & 15;

    float4 acc[4];
    #pragma unroll
    for (int i = 0; i < 4; i++) acc[i] = make_float4(0.f, 0.f, 0.f, 0.f);

    const int xr = t >> 4, xn = t & 15;
    const int wc = t >> 2, wq = t & 3;

    for (int cc0 = 0; cc0 < NC; cc0 += 16) {
        *(float4*)&Xs[xr][xn * 4] =
            *(const float4*)&x[(b*NC + cc0 + xr)*NN + n0 + xn*4];
        float4 wv = *(const float4*)&Wm[(c0 + wc)*NC + cc0 + wq*4];
        Ws[wq*4 + 0][wc] = wv.x;
        Ws[wq*4 + 1][wc] = wv.y;
        Ws[wq*4 + 2][wc] = wv.z;
        Ws[wq*4 + 3][wc] = wv.w;
        __syncthreads();

        #pragma unroll
        for (int cc = 0; cc < 16; cc++) {
            float4 xv  = *(float4*)&Xs[cc][ty * 4];
            float4 wvv = *(float4*)&Ws[cc][tx * 4];
            fma4(acc[0], xv.x, wvv);
            fma4(acc[1], xv.y, wvv);
            fma4(acc[2], xv.z, wvv);
            fma4(acc[3], xv.w, wvv);
        }
        __syncthreads();
    }

    if (w == 2) {
        float* a = (float*)acc;  // a[i*4 + j]
        #pragma unroll
        for (int j = 0; j < 4; j++) {
            uint2 pv;
            pv.x = pack2(a[0*4 + j], a[1*4 + j]);
            pv.y = pack2(a[2*4 + j], a[3*4 + j]);
            *(uint2*)&dst[(size_t)(b*NC + c0 + tx*4 + j)*NN + n0 + ty*4] = pv;
        }
    } else {
        #pragma unroll
        for (int i = 0; i < 4; i++) {
            uint2 pv;
            pv.x = pack2(acc[i].x, acc[i].y);
            pv.y = pack2(acc[i].z, acc[i].w);
            *(uint2*)&dst[(size_t)(b*NN + n0 + ty*4 + i)*NC + c0 + tx*4] = pv;
        }
    }
}

// ---------------------------------------------------------------------------
// Fused flash attention (fp16 mma.sync, Q hoisted, reg softmax,
// cp.async 2-stage K/V pipeline). grid (NN/64, NB), 256 threads (8 warps).
// ---------------------------------------------------------------------------
__global__ __launch_bounds__(256, 1)
void flash_kernel(const float* __restrict__ x,
                  const float* __restrict__ gamma,
                  float* __restrict__ out)
{
    extern __shared__ char smem[];
    const uint32_t sb = smem_u32(smem);
    float* pmax   = (float*)(smem + OFF_PMAX);   // [2][64]
    float* psum   = (float*)(smem + OFF_PSUM);   // [2][64]
    float* s_scal = (float*)(smem + OFF_SCAL);   // [64]
    float* l_row  = (float*)(smem + OFF_LROW);   // [64]

    const int b    = blockIdx.y;
    const int n0   = blockIdx.x * 64;
    const int t    = threadIdx.x;
    const int w    = t >> 5;      // 0..7
    const int lane = t & 31;
    const int gid  = lane >> 2;   // 0..7
    const int tig  = lane & 3;    // 0..3
    const int wr   = w >> 1;      // 0..3
    const int wcl  = w & 1;       // 0..1
    const int lrow = lane & 15;
    const int lk   = (lane >> 4) * 8;

    // per-thread load coords (reused each tile)
    const int kr = t >> 5, kq = t & 31;   // K: 8 rows/pass, 32 quads
    const int vc = t >> 3, vu = t & 7;    // V: 32 ch-rows/pass, 8 quads

    const __half* kg_b = g_k + (size_t)b*NN*NC;
    const __half* vg_b = g_v + (size_t)b*NC*NN;

    // load Q tile (64 x 256 fp16) to smem (synchronous; once)
    {
        const uint4* qg = (const uint4*)(g_q + (size_t)(b*NN + n0)*NC);
        #pragma unroll
        for (int it = 0; it < 8; it++) {
            int i = t + it*256;
            int r = i >> 5, gq = i & 31;
            *(uint4*)(smem + OFF_Q + r*(SQK*2) + gq*16) = qg[i];
        }
    }

    // prefetch tile 0 into stage 0
    {
        const __half* kgp = kg_b;
        const __half* vgp = vg_b;
        #pragma unroll
        for (int it = 0; it < 8; it++) {
            int r = kr + it*8;
            cp16(sb + OFF_K + r*(SQK*2) + kq*16, kgp + (size_t)r*NC + kq*8);
        }
        #pragma unroll
        for (int it = 0; it < 8; it++) {
            int c = vc + it*32;
            cp16(sb + OFF_V + c*(SVP*2) + vu*16, vgp + (size_t)c*NN + vu*8);
        }
        CP_COMMIT();
    }
    __syncthreads();   // Q visible

    // hoist Q fragments: rows 16*wr..+16, all 256 d (16 k-steps)
    uint32_t qf[16][4];
    {
        const uint32_t qa = sb + OFF_Q + ((16*wr + lrow)*SQK + lk)*2;
        #pragma unroll
        for (int s = 0; s < 16; s++)
            ldsm4(qf[s][0], qf[s][1], qf[s][2], qf[s][3], qa + 32*s);
    }

    const int r0 = 16*wr + gid;          // S rows r0, r0+8
    float m_prev[2] = {-INFINITY, -INFINITY};
    float l_acc[2]  = {0.f, 0.f};

    float o[2][8][4];
    #pragma unroll
    for (int mt = 0; mt < 2; mt++)
        #pragma unroll
        for (int nt = 0; nt < 8; nt++)
            #pragma unroll
            for (int r = 0; r < 4; r++) o[mt][nt][r] = 0.f;

    const uint32_t ka_off = ((32*wcl + lrow)*SQK + lk)*2;
    const uint32_t va_off = ((32*w + lrow)*SVP + lk)*2;
    uint32_t pa_base[4];
    #pragma unroll
    for (int jq = 0; jq < 4; jq++)
        pa_base[jq] = sb + OFF_P + ((16*jq + lrow)*SVP + lk)*2;

    for (int kt = 0; kt < 64; kt++) {
        // prefetch next tile into other stage, then wait for this tile
        if (kt < 63) {
            const int stage = (kt + 1) & 1;
            const __half* kgp = kg_b + (size_t)(kt + 1)*64*NC;
            const __half* vgp = vg_b + (size_t)(kt + 1)*64;
            const uint32_t kbase = sb + OFF_K + stage*KSTAGE;
            const uint32_t vbase = sb + OFF_V + stage*VSTAGE;
            #pragma unroll
            for (int it = 0; it < 8; it++) {
                int r = kr + it*8;
                cp16(kbase + r*(SQK*2) + kq*16, kgp + (size_t)r*NC + kq*8);
            }
            #pragma unroll
            for (int it = 0; it < 8; it++) {
                int c = vc + it*32;
                cp16(vbase + c*(SVP*2) + vu*16, vgp + (size_t)c*NN + vu*8);
            }
            CP_COMMIT();
            CP_WAIT(1);
        } else {
            CP_WAIT(0);
        }
        __syncthreads();   // bar1: this tile's K/V visible to all

        const uint32_t ka_base = sb + OFF_K + (kt & 1)*KSTAGE + ka_off;
        const uint32_t va_base = sb + OFF_V + (kt & 1)*VSTAGE + va_off;

        // --- S = Q K^T : warp tile 16x32 (4 n-tiles) ---
        float sacc[4][4];
        #pragma unroll
        for (int j = 0; j < 4; j++)
            #pragma unroll
            for (int r = 0; r < 4; r++) sacc[j][r] = 0.f;

        #pragma unroll
        for (int s = 0; s < 16; s++) {
            uint32_t b0, b1, b2, b3, c0, c1, c2, c3;
            ldsm4(b0, b1, b2, b3, ka_base + 32*s);
            ldsm4(c0, c1, c2, c3, ka_base + 16*(SQK*2) + 32*s);
            mma_f16(sacc[0], qf[s], b0, b2);
            mma_f16(sacc[1], qf[s], b1, b3);
            mma_f16(sacc[2], qf[s], c0, c2);
            mma_f16(sacc[3], qf[s], c1, c3);
        }

        // warp-partial row max
        {
            float mx0 = fmaxf(fmaxf(sacc[0][0], sacc[0][1]), fmaxf(sacc[1][0], sacc[1][1]));
            mx0 = fmaxf(mx0, fmaxf(fmaxf(sacc[2][0], sacc[2][1]), fmaxf(sacc[3][0], sacc[3][1])));
            float mx1 = fmaxf(fmaxf(sacc[0][2], sacc[0][3]), fmaxf(sacc[1][2], sacc[1][3]));
            mx1 = fmaxf(mx1, fmaxf(fmaxf(sacc[2][2], sacc[2][3]), fmaxf(sacc[3][2], sacc[3][3])));
            mx0 = fmaxf(mx0, __shfl_xor_sync(0xffffffffu, mx0, 1));
            mx0 = fmaxf(mx0, __shfl_xor_sync(0xffffffffu, mx0, 2));
            mx1 = fmaxf(mx1, __shfl_xor_sync(0xffffffffu, mx1, 1));
            mx1 = fmaxf(mx1, __shfl_xor_sync(0xffffffffu, mx1, 2));
            if (tig == 0) {
                pmax[wcl*64 + r0]     = mx0;
                pmax[wcl*64 + r0 + 8] = mx1;
            }
        }
        __syncthreads();   // bar2

        // --- softmax in registers ---
        float corr0, corr1;
        {
            float m_new0 = fmaxf(m_prev[0], fmaxf(pmax[r0],     pmax[64 + r0]));
            float m_new1 = fmaxf(m_prev[1], fmaxf(pmax[r0 + 8], pmax[64 + r0 + 8]));
            corr0 = __expf(m_prev[0] - m_new0);
            corr1 = __expf(m_prev[1] - m_new1);
            m_prev[0] = m_new0; m_prev[1] = m_new1;

            float ps0 = 0.f, ps1 = 0.f;
            #pragma unroll
            for (int j = 0; j < 4; j++) {
                float p0 = __expf(sacc[j][0] - m_new0);
                float p1 = __expf(sacc[j][1] - m_new0);
                float p2 = __expf(sacc[j][2] - m_new1);
                float p3 = __expf(sacc[j][3] - m_new1);
                ps0 += p0 + p1; ps1 += p2 + p3;
                int cj = 32*wcl + 8*j + 2*tig;
                *(uint32_t*)(smem + OFF_P + (r0*SVP + cj)*2)       = pack2(p0, p1);
                *(uint32_t*)(smem + OFF_P + ((r0 + 8)*SVP + cj)*2) = pack2(p2, p3);
            }
            ps0 += __shfl_xor_sync(0xffffffffu, ps0, 1);
            ps0 += __shfl_xor_sync(0xffffffffu, ps0, 2);
            ps1 += __shfl_xor_sync(0xffffffffu, ps1, 1);
            ps1 += __shfl_xor_sync(0xffffffffu, ps1, 2);
            if (tig == 0) {
                psum[wcl*64 + r0]     = ps0;
                psum[wcl*64 + r0 + 8] = ps1;
            }
            if (wcl == 0 && tig == 0) {
                s_scal[r0]     = corr0;
                s_scal[r0 + 8] = corr1;
            }
        }
        __syncthreads();   // bar3

        l_acc[0] = l_acc[0]*corr0 + psum[r0]     + psum[64 + r0];
        l_acc[1] = l_acc[1]*corr1 + psum[r0 + 8] + psum[64 + r0 + 8];

        // --- O^T = O^T*corr + V^T P^T ---
        #pragma unroll
        for (int nt = 0; nt < 8; nt++) {
            float s0 = s_scal[8*nt + 2*tig];
            float s1 = s_scal[8*nt + 2*tig + 1];
            #pragma unroll
            for (int mt = 0; mt < 2; mt++) {
                o[mt][nt][0] *= s0; o[mt][nt][1] *= s1;
                o[mt][nt][2] *= s0; o[mt][nt][3] *= s1;
            }
        }
        #pragma unroll
        for (int s = 0; s < 4; s++) {
            uint32_t av0[4], av1[4];
            ldsm4(av0[0], av0[1], av0[2], av0[3], va_base + 32*s);
            ldsm4(av1[0], av1[1], av1[2], av1[3], va_base + 16*(SVP*2) + 32*s);
            #pragma unroll
            for (int jq = 0; jq < 4; jq++) {
                uint32_t p0, p1, p2, p3;
                ldsm4(p0, p1, p2, p3, pa_base[jq] + 32*s);
                mma_f16(o[0][2*jq],     av0, p0, p2);
                mma_f16(o[0][2*jq + 1], av0, p1, p3);
                mma_f16(o[1][2*jq],     av1, p0, p2);
                mma_f16(o[1][2*jq + 1], av1, p1, p3);
            }
        }
        __syncthreads();   // bar4: V/P consumed; buffer reuse + P rewrite safe
    }

    if (wcl == 0 && tig == 0) {
        l_row[r0]     = l_acc[0];
        l_row[r0 + 8] = l_acc[1];
    }
    __syncthreads();

    // --- O^T/l to Ot smem (channel-major already) ---
    float* Ot = (float*)(smem + OFF_Q);  // 256*68*4 = 69632, loop is done
    #pragma unroll
    for (int nt = 0; nt < 8; nt++) {
        int q = 8*nt + 2*tig;
        float li0 = __fdividef(1.f, l_row[q]);
        float li1 = __fdividef(1.f, l_row[q + 1]);
        #pragma unroll
        for (int mt = 0; mt < 2; mt++) {
            int c = 32*w + 16*mt + gid;
            Ot[c*SSTR + q]         = o[mt][nt][0] * li0;
            Ot[c*SSTR + q + 1]     = o[mt][nt][1] * li1;
            Ot[(c+8)*SSTR + q]     = o[mt][nt][2] * li0;
            Ot[(c+8)*SSTR + q + 1] = o[mt][nt][3] * li1;
        }
    }
    __syncthreads();

    const float g = gamma[0];
    #pragma unroll
    for (int pass = 0; pass < 4; pass++) {
        int c = pass*64 + (t >> 2);
        #pragma unroll
        for (int j = 0; j < 4; j++) {
            int f4 = (t & 3) + j*4;
            float4 ov = *(float4*)(Ot + c*SSTR + f4*4);
            float4 xv = *(const float4*)(x + (size_t)(b*NC + c)*NN + n0 + f4*4);
            float4 r;
            r.x = g*ov.x + xv.x; r.y = g*ov.y + xv.y;
            r.z = g*ov.z + xv.z; r.w = g*ov.w + xv.w;
            *(float4*)(out + (size_t)(b*NC + c)*NN + n0 + f4*4) = r;
        }
    }
}

// ---------------------------------------------------------------------------

extern "C" void kernel_launch(void* const* d_in, const int* in_sizes, int n_in,
                              void* d_out, int out_size)
{
    const float* x     = (const float*)d_in[0];
    const float* Wq    = (const float*)d_in[1];
    const float* Wk    = (const float*)d_in[2];
    const float* Wv    = (const float*)d_in[3];
    const float* gamma = (const float*)d_in[4];
    float* out = (float*)d_out;

    cudaFuncSetAttribute(flash_kernel,
                         cudaFuncAttributeMaxDynamicSharedMemorySize, SMEM_BYTES);

    dim3 gp(NN/64, NC/64, 3*NB);
    qkv_proj_kernel<<<gp, 256>>>(x, Wq, Wk, Wv);

    dim3 gf(NN/64, NB);
    flash_kernel<<<gf, 256, SMEM_BYTES>>>(x, gamma, out);
}

// round 12
// speedup vs baseline: 2.6429x; 1.3254x over previous
#include <cuda_runtime.h>
#include <cuda_fp16.h>
#include <cstdint>
#include <math.h>

#define NB 4
#define NC 256
#define NN 4096

// fp16 smem strides (elements)
#define SQK 264    // Q/K rows: 528B -> ldmatrix conflict-free
#define SVP 72     // V / P rows: 144B -> conflict-free
#define SSTR 68    // fp32 Ot stride

// flash smem byte offsets (K/V are 2-stage ring buffers)
#define OFF_Q    0
#define OFF_K    33792
#define KSTAGE   33792
#define OFF_V    101376
#define VSTAGE   36864
#define OFF_P    175104
#define OFF_PMAX 184320
#define OFF_PSUM 184832
#define OFF_SCAL 185344
#define OFF_LROW 185600
#define SMEM_BYTES 185856

// gemm smem: A tile + B tile, 64 x 264 fp16 each
#define GEMM_SMEM (2*64*SQK*2)

// scratch: q,k as (B,N,C) fp16; v as (B,C,N) fp16; xh as (B,N,C) fp16
__device__ __half g_q[NB*NN*NC];
__device__ __half g_k[NB*NN*NC];
__device__ __half g_v[NB*NN*NC];
__device__ __half g_xh[NB*NN*NC];
__device__ __half g_wh[3*NC*NC];

__device__ __forceinline__ uint32_t pack2(float a, float b) {
    __half2 h = __floats2half2_rn(a, b);
    return *(uint32_t*)&h;
}
__device__ __forceinline__ uint32_t smem_u32(const void* p) {
    uint32_t a;
    asm("{ .reg .u64 t; cvta.to.shared.u64 t, %1; cvt.u32.u64 %0, t; }" : "=r"(a) : "l"(p));
    return a;
}
__device__ __forceinline__ void ldsm4(uint32_t& r0, uint32_t& r1, uint32_t& r2,
                                      uint32_t& r3, uint32_t addr) {
    asm volatile("ldmatrix.sync.aligned.m8n8.x4.shared.b16 {%0,%1,%2,%3}, [%4];"
                 : "=r"(r0), "=r"(r1), "=r"(r2), "=r"(r3) : "r"(addr));
}
__device__ __forceinline__ void mma_f16(float* c, const uint32_t* a,
                                        uint32_t b0, uint32_t b1) {
    asm volatile(
        "mma.sync.aligned.m16n8k16.row.col.f32.f16.f16.f32 "
        "{%0,%1,%2,%3}, {%4,%5,%6,%7}, {%8,%9}, {%0,%1,%2,%3};"
        : "+f"(c[0]), "+f"(c[1]), "+f"(c[2]), "+f"(c[3])
        : "r"(a[0]), "r"(a[1]), "r"(a[2]), "r"(a[3]), "r"(b0), "r"(b1));
}
__device__ __forceinline__ void cp16(uint32_t saddr, const void* gaddr) {
    asm volatile("cp.async.cg.shared.global [%0], [%1], 16;"
                 :: "r"(saddr), "l"(gaddr));
}
#define CP_COMMIT()   asm volatile("cp.async.commit_group;" ::: "memory")
#define CP_WAIT(n)    asm volatile("cp.async.wait_group %0;" :: "n"(n) : "memory")

// ---------------------------------------------------------------------------
// W -> fp16
// ---------------------------------------------------------------------------
__global__ void wconv_kernel(const float* __restrict__ Wq,
                             const float* __restrict__ Wk,
                             const float* __restrict__ Wv)
{
    int i = blockIdx.x * blockDim.x + threadIdx.x;   // < 3*65536
    const float* src = (i < 65536) ? Wq : (i < 131072) ? Wk : Wv;
    int o = i & 65535;
    g_wh[i] = __float2half(src[o]);
}

// ---------------------------------------------------------------------------
// x (B,C,N) fp32 -> xh (B,N,C) fp16  (64x64 tiles through smem)
// ---------------------------------------------------------------------------
__global__ __launch_bounds__(256)
void xt_kernel(const float* __restrict__ x)
{
    __shared__ float ts[64][65];
    const int n0 = blockIdx.x * 64;
    const int c0 = blockIdx.y * 64;
    const int b  = blockIdx.z;
    const int t  = threadIdx.x;

    #pragma unroll
    for (int it = 0; it < 4; it++) {
        int i = t + it*256;
        int c = i >> 4, nq = i & 15;
        float4 v = *(const float4*)&x[(size_t)(b*NC + c0 + c)*NN + n0 + nq*4];
        ts[nq*4 + 0][c] = v.x;
        ts[nq*4 + 1][c] = v.y;
        ts[nq*4 + 2][c] = v.z;
        ts[nq*4 + 3][c] = v.w;
    }
    __syncthreads();

    #pragma unroll
    for (int it = 0; it < 2; it++) {
        int i = t + it*256;
        int n = i >> 3, cq = i & 7;
        uint4 o;
        o.x = pack2(ts[n][cq*8 + 0], ts[n][cq*8 + 1]);
        o.y = pack2(ts[n][cq*8 + 2], ts[n][cq*8 + 3]);
        o.z = pack2(ts[n][cq*8 + 4], ts[n][cq*8 + 5]);
        o.w = pack2(ts[n][cq*8 + 6], ts[n][cq*8 + 7]);
        *(uint4*)&g_xh[(size_t)(b*NN + n0 + n)*NC + c0 + cq*8] = o;
    }
}

// ---------------------------------------------------------------------------
// QKV projection GEMM (fp16 mma): D = A(64xK=256) * B(64xK=256)^T per tile.
// z=0: q = xh * Wq^T   (rows = flat b*N+n, cols = c_out)  -> g_q (B,N,C)
// z=1: k = xh * Wk^T                                      -> g_k (B,N,C)
// z=2: v = Wv * xh^T   (rows = c, cols = flat n)          -> g_v (B,C,N)
// grid (256, 4, 3), 256 threads (8 warps, 4x2).
// ---------------------------------------------------------------------------
__global__ __launch_bounds__(256, 3)
void qkv_mma_kernel()
{
    extern __shared__ char smem[];
    const uint32_t sb = smem_u32(smem);
    const uint32_t SB_OFF = 64*SQK*2;

    const int bx = blockIdx.x;   // 256 tiles
    const int by = blockIdx.y;   // 4 tiles
    const int z  = blockIdx.z;

    const __half* Aptr;
    const __half* Bptr;
    if (z < 2) {
        Aptr = g_xh + (size_t)bx*64*NC;
        Bptr = g_wh + (size_t)z*65536 + (size_t)by*64*NC;
    } else {
        Aptr = g_wh + 2*65536 + (size_t)by*64*NC;
        Bptr = g_xh + (size_t)bx*64*NC;
    }

    const int t    = threadIdx.x;
    const int w    = t >> 5;
    const int lane = t & 31;
    const int gid  = lane >> 2;
    const int tig  = lane & 3;
    const int wr   = w >> 1;      // 0..3 (m)
    const int wcl  = w & 1;       // 0..1 (n)
    const int lrow = lane & 15;
    const int lk   = (lane >> 4) * 8;

    // load A, B tiles (64 rows x 512B each)
    #pragma unroll
    for (int it = 0; it < 8; it++) {
        int i = t + it*256;
        int r = i >> 5, gq = i & 31;
        *(uint4*)(smem + r*(SQK*2) + gq*16) =
            ((const uint4*)(Aptr + (size_t)r*NC))[gq];
        *(uint4*)(smem + SB_OFF + r*(SQK*2) + gq*16) =
            ((const uint4*)(Bptr + (size_t)r*NC))[gq];
    }
    __syncthreads();

    float sacc[4][4];
    #pragma unroll
    for (int j = 0; j < 4; j++)
        #pragma unroll
        for (int r = 0; r < 4; r++) sacc[j][r] = 0.f;

    const uint32_t aa = sb + ((16*wr + lrow)*SQK + lk)*2;
    const uint32_t ba = sb + SB_OFF + ((32*wcl + lrow)*SQK + lk)*2;

    #pragma unroll
    for (int s = 0; s < 16; s++) {
        uint32_t a[4], b0, b1, b2, b3, c0, c1, c2, c3;
        ldsm4(a[0], a[1], a[2], a[3], aa + 32*s);
        ldsm4(b0, b1, b2, b3, ba + 32*s);
        ldsm4(c0, c1, c2, c3, ba + 16*(SQK*2) + 32*s);
        mma_f16(sacc[0], a, b0, b2);
        mma_f16(sacc[1], a, b1, b3);
        mma_f16(sacc[2], a, c0, c2);
        mma_f16(sacc[3], a, c1, c3);
    }

    // store: rows 16*wr + gid (+8); cols 32*wcl + 8j + 2tig (+1)
    #pragma unroll
    for (int mh = 0; mh < 2; mh++) {
        const int mrow = 16*wr + gid + 8*mh;
        if (z < 2) {
            __half* D = (z == 0) ? g_q : g_k;
            const size_t rb = ((size_t)bx*64 + mrow)*NC + by*64;
            #pragma unroll
            for (int j = 0; j < 4; j++)
                *(uint32_t*)&D[rb + 32*wcl + 8*j + 2*tig] =
                    pack2(sacc[j][2*mh], sacc[j][2*mh + 1]);
        } else {
            const int bb = bx >> 6;
            const int nl = (bx & 63)*64;
            const size_t rb = (size_t)bb*NC*NN + ((size_t)by*64 + mrow)*NN + nl;
            #pragma unroll
            for (int j = 0; j < 4; j++)
                *(uint32_t*)&g_v[rb + 32*wcl + 8*j + 2*tig] =
                    pack2(sacc[j][2*mh], sacc[j][2*mh + 1]);
        }
    }
}

// ---------------------------------------------------------------------------
// Fused flash attention (fp16 mma.sync, Q hoisted, reg softmax,
// cp.async 2-stage K/V pipeline). grid (NN/64, NB), 256 threads (8 warps).
// ---------------------------------------------------------------------------
__global__ __launch_bounds__(256, 1)
void flash_kernel(const float* __restrict__ x,
                  const float* __restrict__ gamma,
                  float* __restrict__ out)
{
    extern __shared__ char smem[];
    const uint32_t sb = smem_u32(smem);
    float* pmax   = (float*)(smem + OFF_PMAX);   // [2][64]
    float* psum   = (float*)(smem + OFF_PSUM);   // [2][64]
    float* s_scal = (float*)(smem + OFF_SCAL);   // [64]
    float* l_row  = (float*)(smem + OFF_LROW);   // [64]

    const int b    = blockIdx.y;
    const int n0   = blockIdx.x * 64;
    const int t    = threadIdx.x;
    const int w    = t >> 5;      // 0..7
    const int lane = t & 31;
    const int gid  = lane >> 2;   // 0..7
    const int tig  = lane & 3;    // 0..3
    const int wr   = w >> 1;      // 0..3
    const int wcl  = w & 1;       // 0..1
    const int lrow = lane & 15;
    const int lk   = (lane >> 4) * 8;

    const int kr = t >> 5, kq = t & 31;   // K loads
    const int vc = t >> 3, vu = t & 7;    // V loads

    const __half* kg_b = g_k + (size_t)b*NN*NC;
    const __half* vg_b = g_v + (size_t)b*NC*NN;

    // load Q tile (64 x 256 fp16) to smem
    {
        const uint4* qg = (const uint4*)(g_q + (size_t)(b*NN + n0)*NC);
        #pragma unroll
        for (int it = 0; it < 8; it++) {
            int i = t + it*256;
            int r = i >> 5, gq = i & 31;
            *(uint4*)(smem + OFF_Q + r*(SQK*2) + gq*16) = qg[i];
        }
    }

    // prefetch tile 0 into stage 0
    {
        #pragma unroll
        for (int it = 0; it < 8; it++) {
            int r = kr + it*8;
            cp16(sb + OFF_K + r*(SQK*2) + kq*16, kg_b + (size_t)r*NC + kq*8);
        }
        #pragma unroll
        for (int it = 0; it < 8; it++) {
            int c = vc + it*32;
            cp16(sb + OFF_V + c*(SVP*2) + vu*16, vg_b + (size_t)c*NN + vu*8);
        }
        CP_COMMIT();
    }
    __syncthreads();   // Q visible

    // hoist Q fragments
    uint32_t qf[16][4];
    {
        const uint32_t qa = sb + OFF_Q + ((16*wr + lrow)*SQK + lk)*2;
        #pragma unroll
        for (int s = 0; s < 16; s++)
            ldsm4(qf[s][0], qf[s][1], qf[s][2], qf[s][3], qa + 32*s);
    }

    const int r0 = 16*wr + gid;
    float m_prev[2] = {-INFINITY, -INFINITY};
    float l_acc[2]  = {0.f, 0.f};

    float o[2][8][4];
    #pragma unroll
    for (int mt = 0; mt < 2; mt++)
        #pragma unroll
        for (int nt = 0; nt < 8; nt++)
            #pragma unroll
            for (int r = 0; r < 4; r++) o[mt][nt][r] = 0.f;

    const uint32_t ka_off = ((32*wcl + lrow)*SQK + lk)*2;
    const uint32_t va_off = ((32*w + lrow)*SVP + lk)*2;
    uint32_t pa_base[4];
    #pragma unroll
    for (int jq = 0; jq < 4; jq++)
        pa_base[jq] = sb + OFF_P + ((16*jq + lrow)*SVP + lk)*2;

    for (int kt = 0; kt < 64; kt++) {
        if (kt < 63) {
            const int stage = (kt + 1) & 1;
            const __half* kgp = kg_b + (size_t)(kt + 1)*64*NC;
            const __half* vgp = vg_b + (size_t)(kt + 1)*64;
            const uint32_t kbase = sb + OFF_K + stage*KSTAGE;
            const uint32_t vbase = sb + OFF_V + stage*VSTAGE;
            #pragma unroll
            for (int it = 0; it < 8; it++) {
                int r = kr + it*8;
                cp16(kbase + r*(SQK*2) + kq*16, kgp + (size_t)r*NC + kq*8);
            }
            #pragma unroll
            for (int it = 0; it < 8; it++) {
                int c = vc + it*32;
                cp16(vbase + c*(SVP*2) + vu*16, vgp + (size_t)c*NN + vu*8);
            }
            CP_COMMIT();
            CP_WAIT(1);
        } else {
            CP_WAIT(0);
        }
        __syncthreads();   // bar1

        const uint32_t ka_base = sb + OFF_K + (kt & 1)*KSTAGE + ka_off;
        const uint32_t va_base = sb + OFF_V + (kt & 1)*VSTAGE + va_off;

        // --- S = Q K^T ---
        float sacc[4][4];
        #pragma unroll
        for (int j = 0; j < 4; j++)
            #pragma unroll
            for (int r = 0; r < 4; r++) sacc[j][r] = 0.f;

        #pragma unroll
        for (int s = 0; s < 16; s++) {
            uint32_t b0, b1, b2, b3, c0, c1, c2, c3;
            ldsm4(b0, b1, b2, b3, ka_base + 32*s);
            ldsm4(c0, c1, c2, c3, ka_base + 16*(SQK*2) + 32*s);
            mma_f16(sacc[0], qf[s], b0, b2);
            mma_f16(sacc[1], qf[s], b1, b3);
            mma_f16(sacc[2], qf[s], c0, c2);
            mma_f16(sacc[3], qf[s], c1, c3);
        }

        // warp-partial row max
        {
            float mx0 = fmaxf(fmaxf(sacc[0][0], sacc[0][1]), fmaxf(sacc[1][0], sacc[1][1]));
            mx0 = fmaxf(mx0, fmaxf(fmaxf(sacc[2][0], sacc[2][1]), fmaxf(sacc[3][0], sacc[3][1])));
            float mx1 = fmaxf(fmaxf(sacc[0][2], sacc[0][3]), fmaxf(sacc[1][2], sacc[1][3]));
            mx1 = fmaxf(mx1, fmaxf(fmaxf(sacc[2][2], sacc[2][3]), fmaxf(sacc[3][2], sacc[3][3])));
            mx0 = fmaxf(mx0, __shfl_xor_sync(0xffffffffu, mx0, 1));
            mx0 = fmaxf(mx0, __shfl_xor_sync(0xffffffffu, mx0, 2));
            mx1 = fmaxf(mx1, __shfl_xor_sync(0xffffffffu, mx1, 1));
            mx1 = fmaxf(mx1, __shfl_xor_sync(0xffffffffu, mx1, 2));
            if (tig == 0) {
                pmax[wcl*64 + r0]     = mx0;
                pmax[wcl*64 + r0 + 8] = mx1;
            }
        }
        __syncthreads();   // bar2

        // --- softmax in registers ---
        float corr0, corr1;
        {
            float m_new0 = fmaxf(m_prev[0], fmaxf(pmax[r0],     pmax[64 + r0]));
            float m_new1 = fmaxf(m_prev[1], fmaxf(pmax[r0 + 8], pmax[64 + r0 + 8]));
            corr0 = __expf(m_prev[0] - m_new0);
            corr1 = __expf(m_prev[1] - m_new1);
            m_prev[0] = m_new0; m_prev[1] = m_new1;

            float ps0 = 0.f, ps1 = 0.f;
            #pragma unroll
            for (int j = 0; j < 4; j++) {
                float p0 = __expf(sacc[j][0] - m_new0);
                float p1 = __expf(sacc[j][1] - m_new0);
                float p2 = __expf(sacc[j][2] - m_new1);
                float p3 = __expf(sacc[j][3] - m_new1);
                ps0 += p0 + p1; ps1 += p2 + p3;
                int cj = 32*wcl + 8*j + 2*tig;
                *(uint32_t*)(smem + OFF_P + (r0*SVP + cj)*2)       = pack2(p0, p1);
                *(uint32_t*)(smem + OFF_P + ((r0 + 8)*SVP + cj)*2) = pack2(p2, p3);
            }
            ps0 += __shfl_xor_sync(0xffffffffu, ps0, 1);
            ps0 += __shfl_xor_sync(0xffffffffu, ps0, 2);
            ps1 += __shfl_xor_sync(0xffffffffu, ps1, 1);
            ps1 += __shfl_xor_sync(0xffffffffu, ps1, 2);
            if (tig == 0) {
                psum[wcl*64 + r0]     = ps0;
                psum[wcl*64 + r0 + 8] = ps1;
            }
            if (wcl == 0 && tig == 0) {
                s_scal[r0]     = corr0;
                s_scal[r0 + 8] = corr1;
            }
        }
        __syncthreads();   // bar3

        l_acc[0] = l_acc[0]*corr0 + psum[r0]     + psum[64 + r0];
        l_acc[1] = l_acc[1]*corr1 + psum[r0 + 8] + psum[64 + r0 + 8];

        // --- O^T = O^T*corr + V^T P^T ---
        #pragma unroll
        for (int nt = 0; nt < 8; nt++) {
            float s0 = s_scal[8*nt + 2*tig];
            float s1 = s_scal[8*nt + 2*tig + 1];
            #pragma unroll
            for (int mt = 0; mt < 2; mt++) {
                o[mt][nt][0] *= s0; o[mt][nt][1] *= s1;
                o[mt][nt][2] *= s0; o[mt][nt][3] *= s1;
            }
        }
        #pragma unroll
        for (int s = 0; s < 4; s++) {
            uint32_t av0[4], av1[4];
            ldsm4(av0[0], av0[1], av0[2], av0[3], va_base + 32*s);
            ldsm4(av1[0], av1[1], av1[2], av1[3], va_base + 16*(SVP*2) + 32*s);
            #pragma unroll
            for (int jq = 0; jq < 4; jq++) {
                uint32_t p0, p1, p2, p3;
                ldsm4(p0, p1, p2, p3, pa_base[jq] + 32*s);
                mma_f16(o[0][2*jq],     av0, p0, p2);
                mma_f16(o[0][2*jq + 1], av0, p1, p3);
                mma_f16(o[1][2*jq],     av1, p0, p2);
                mma_f16(o[1][2*jq + 1], av1, p1, p3);
            }
        }
        __syncthreads();   // bar4
    }

    if (wcl == 0 && tig == 0) {
        l_row[r0]     = l_acc[0];
        l_row[r0 + 8] = l_acc[1];
    }
    __syncthreads();

    // --- O^T/l to Ot smem ---
    float* Ot = (float*)(smem + OFF_Q);
    #pragma unroll
    for (int nt = 0; nt < 8; nt++) {
        int q = 8*nt + 2*tig;
        float li0 = __fdividef(1.f, l_row[q]);
        float li1 = __fdividef(1.f, l_row[q + 1]);
        #pragma unroll
        for (int mt = 0; mt < 2; mt++) {
            int c = 32*w + 16*mt + gid;
            Ot[c*SSTR + q]         = o[mt][nt][0] * li0;
            Ot[c*SSTR + q + 1]     = o[mt][nt][1] * li1;
            Ot[(c+8)*SSTR + q]     = o[mt][nt][2] * li0;
            Ot[(c+8)*SSTR + q + 1] = o[mt][nt][3] * li1;
        }
    }
    __syncthreads();

    const float g = gamma[0];
    #pragma unroll
    for (int pass = 0; pass < 4; pass++) {
        int c = pass*64 + (t >> 2);
        #pragma unroll
        for (int j = 0; j < 4; j++) {
            int f4 = (t & 3) + j*4;
            float4 ov = *(float4*)(Ot + c*SSTR + f4*4);
            float4 xv = *(const float4*)(x + (size_t)(b*NC + c)*NN + n0 + f4*4);
            float4 r;
            r.x = g*ov.x + xv.x; r.y = g*ov.y + xv.y;
            r.z = g*ov.z + xv.z; r.w = g*ov.w + xv.w;
            *(float4*)(out + (size_t)(b*NC + c)*NN + n0 + f4*4) = r;
        }
    }
}

// ---------------------------------------------------------------------------

extern "C" void kernel_launch(void* const* d_in, const int* in_sizes, int n_in,
                              void* d_out, int out_size)
{
    const float* x     = (const float*)d_in[0];
    const float* Wq    = (const float*)d_in[1];
    const float* Wk    = (const float*)d_in[2];
    const float* Wv    = (const float*)d_in[3];
    const float* gamma = (const float*)d_in[4];
    float* out = (float*)d_out;

    cudaFuncSetAttribute(flash_kernel,
                         cudaFuncAttributeMaxDynamicSharedMemorySize, SMEM_BYTES);
    cudaFuncSetAttribute(qkv_mma_kernel,
                         cudaFuncAttributeMaxDynamicSharedMemorySize, GEMM_SMEM);

    wconv_kernel<<<3*65536/256, 256>>>(Wq, Wk, Wv);

    dim3 gt(NN/64, NC/64, NB);
    xt_kernel<<<gt, 256>>>(x);

    dim3 gg(256, 4, 3);
    qkv_mma_kernel<<<gg, 256, GEMM_SMEM>>>();

    dim3 gf(NN/64, NB);
    flash_kernel<<<gf, 256, SMEM_BYTES>>>(x, gamma, out);
}

// round 13
// speedup vs baseline: 2.9410x; 1.1128x over previous
#include <cuda_runtime.h>
#include <cuda_fp16.h>
#include <cstdint>
#include <math.h>

#define NB 4
#define NC 256
#define NN 4096

// fp16 smem strides (elements)
#define SQK 264    // Q/K rows: 528B -> ldmatrix conflict-free
#define SVP 72     // V / P rows: 144B -> conflict-free
#define SSTR2 132  // fp32 Ot stride (128 queries + pad)

// flash smem byte offsets (BM=128; K 2-stage, V 1-stage)
#define OFF_Q    0
#define OFF_K    67584
#define KSTAGE   33792
#define OFF_V    135168
#define OFF_P    172032
#define OFF_PMAX 190464
#define OFF_PSUM 191488
#define OFF_SCAL 192512
#define OFF_LROW 193024
#define SMEM_BYTES 193536

// gemm smem: A tile + B tile, 64 x 264 fp16 each
#define GEMM_SMEM (2*64*SQK*2)

// scratch: q,k as (B,N,C) fp16; v as (B,C,N) fp16; xh as (B,N,C) fp16
__device__ __half g_q[NB*NN*NC];
__device__ __half g_k[NB*NN*NC];
__device__ __half g_v[NB*NN*NC];
__device__ __half g_xh[NB*NN*NC];
__device__ __half g_wh[3*NC*NC];

__device__ __forceinline__ uint32_t pack2(float a, float b) {
    __half2 h = __floats2half2_rn(a, b);
    return *(uint32_t*)&h;
}
__device__ __forceinline__ uint32_t smem_u32(const void* p) {
    uint32_t a;
    asm("{ .reg .u64 t; cvta.to.shared.u64 t, %1; cvt.u32.u64 %0, t; }" : "=r"(a) : "l"(p));
    return a;
}
__device__ __forceinline__ void ldsm4(uint32_t& r0, uint32_t& r1, uint32_t& r2,
                                      uint32_t& r3, uint32_t addr) {
    asm volatile("ldmatrix.sync.aligned.m8n8.x4.shared.b16 {%0,%1,%2,%3}, [%4];"
                 : "=r"(r0), "=r"(r1), "=r"(r2), "=r"(r3) : "r"(addr));
}
__device__ __forceinline__ void mma_f16(float* c, const uint32_t* a,
                                        uint32_t b0, uint32_t b1) {
    asm volatile(
        "mma.sync.aligned.m16n8k16.row.col.f32.f16.f16.f32 "
        "{%0,%1,%2,%3}, {%4,%5,%6,%7}, {%8,%9}, {%0,%1,%2,%3};"
        : "+f"(c[0]), "+f"(c[1]), "+f"(c[2]), "+f"(c[3])
        : "r"(a[0]), "r"(a[1]), "r"(a[2]), "r"(a[3]), "r"(b0), "r"(b1));
}
__device__ __forceinline__ void cp16(uint32_t saddr, const void* gaddr) {
    asm volatile("cp.async.cg.shared.global [%0], [%1], 16;"
                 :: "r"(saddr), "l"(gaddr));
}
#define CP_COMMIT()   asm volatile("cp.async.commit_group;" ::: "memory")
#define CP_WAIT(n)    asm volatile("cp.async.wait_group %0;" :: "n"(n) : "memory")

// ---------------------------------------------------------------------------
// W -> fp16
// ---------------------------------------------------------------------------
__global__ void wconv_kernel(const float* __restrict__ Wq,
                             const float* __restrict__ Wk,
                             const float* __restrict__ Wv)
{
    int i = blockIdx.x * blockDim.x + threadIdx.x;
    const float* src = (i < 65536) ? Wq : (i < 131072) ? Wk : Wv;
    int o = i & 65535;
    g_wh[i] = __float2half(src[o]);
}

// ---------------------------------------------------------------------------
// x (B,C,N) fp32 -> xh (B,N,C) fp16  (64x64 tiles through smem)
// ---------------------------------------------------------------------------
__global__ __launch_bounds__(256)
void xt_kernel(const float* __restrict__ x)
{
    __shared__ float ts[64][65];
    const int n0 = blockIdx.x * 64;
    const int c0 = blockIdx.y * 64;
    const int b  = blockIdx.z;
    const int t  = threadIdx.x;

    #pragma unroll
    for (int it = 0; it < 4; it++) {
        int i = t + it*256;
        int c = i >> 4, nq = i & 15;
        float4 v = *(const float4*)&x[(size_t)(b*NC + c0 + c)*NN + n0 + nq*4];
        ts[nq*4 + 0][c] = v.x;
        ts[nq*4 + 1][c] = v.y;
        ts[nq*4 + 2][c] = v.z;
        ts[nq*4 + 3][c] = v.w;
    }
    __syncthreads();

    #pragma unroll
    for (int it = 0; it < 2; it++) {
        int i = t + it*256;
        int n = i >> 3, cq = i & 7;
        uint4 o;
        o.x = pack2(ts[n][cq*8 + 0], ts[n][cq*8 + 1]);
        o.y = pack2(ts[n][cq*8 + 2], ts[n][cq*8 + 3]);
        o.z = pack2(ts[n][cq*8 + 4], ts[n][cq*8 + 5]);
        o.w = pack2(ts[n][cq*8 + 6], ts[n][cq*8 + 7]);
        *(uint4*)&g_xh[(size_t)(b*NN + n0 + n)*NC + c0 + cq*8] = o;
    }
}

// ---------------------------------------------------------------------------
// QKV projection GEMM (fp16 mma). grid (256, 4, 3), 256 threads.
// ---------------------------------------------------------------------------
__global__ __launch_bounds__(256, 3)
void qkv_mma_kernel()
{
    extern __shared__ char smem[];
    const uint32_t sb = smem_u32(smem);
    const uint32_t SB_OFF = 64*SQK*2;

    const int bx = blockIdx.x;
    const int by = blockIdx.y;
    const int z  = blockIdx.z;

    const __half* Aptr;
    const __half* Bptr;
    if (z < 2) {
        Aptr = g_xh + (size_t)bx*64*NC;
        Bptr = g_wh + (size_t)z*65536 + (size_t)by*64*NC;
    } else {
        Aptr = g_wh + 2*65536 + (size_t)by*64*NC;
        Bptr = g_xh + (size_t)bx*64*NC;
    }

    const int t    = threadIdx.x;
    const int w    = t >> 5;
    const int lane = t & 31;
    const int gid  = lane >> 2;
    const int tig  = lane & 3;
    const int wr   = w >> 1;
    const int wcl  = w & 1;
    const int lrow = lane & 15;
    const int lk   = (lane >> 4) * 8;

    #pragma unroll
    for (int it = 0; it < 8; it++) {
        int i = t + it*256;
        int r = i >> 5, gq = i & 31;
        *(uint4*)(smem + r*(SQK*2) + gq*16) =
            ((const uint4*)(Aptr + (size_t)r*NC))[gq];
        *(uint4*)(smem + SB_OFF + r*(SQK*2) + gq*16) =
            ((const uint4*)(Bptr + (size_t)r*NC))[gq];
    }
    __syncthreads();

    float sacc[4][4];
    #pragma unroll
    for (int j = 0; j < 4; j++)
        #pragma unroll
        for (int r = 0; r < 4; r++) sacc[j][r] = 0.f;

    const uint32_t aa = sb + ((16*wr + lrow)*SQK + lk)*2;
    const uint32_t ba = sb + SB_OFF + ((32*wcl + lrow)*SQK + lk)*2;

    #pragma unroll
    for (int s = 0; s < 16; s++) {
        uint32_t a[4], b0, b1, b2, b3, c0, c1, c2, c3;
        ldsm4(a[0], a[1], a[2], a[3], aa + 32*s);
        ldsm4(b0, b1, b2, b3, ba + 32*s);
        ldsm4(c0, c1, c2, c3, ba + 16*(SQK*2) + 32*s);
        mma_f16(sacc[0], a, b0, b2);
        mma_f16(sacc[1], a, b1, b3);
        mma_f16(sacc[2], a, c0, c2);
        mma_f16(sacc[3], a, c1, c3);
    }

    #pragma unroll
    for (int mh = 0; mh < 2; mh++) {
        const int mrow = 16*wr + gid + 8*mh;
        if (z < 2) {
            __half* D = (z == 0) ? g_q : g_k;
            const size_t rb = ((size_t)bx*64 + mrow)*NC + by*64;
            #pragma unroll
            for (int j = 0; j < 4; j++)
                *(uint32_t*)&D[rb + 32*wcl + 8*j + 2*tig] =
                    pack2(sacc[j][2*mh], sacc[j][2*mh + 1]);
        } else {
            const int bb = bx >> 6;
            const int nl = (bx & 63)*64;
            const size_t rb = (size_t)bb*NC*NN + ((size_t)by*64 + mrow)*NN + nl;
            #pragma unroll
            for (int j = 0; j < 4; j++)
                *(uint32_t*)&g_v[rb + 32*wcl + 8*j + 2*tig] =
                    pack2(sacc[j][2*mh], sacc[j][2*mh + 1]);
        }
    }
}

// ---------------------------------------------------------------------------
// Fused flash attention, BM=128, BN=64, 512 threads (16 warps), 1 wave.
// S: warp grid 8(wr) x 2(wcl), warp tile 16x32, Q via ldmatrix.
// PV: warp (wd = w>>1) owns d-rows [32wd,+32); (qh = w&1) owns queries [64qh,+64).
// K double-buffered cp.async; V single-buffered, copy overlaps next S+softmax.
// ---------------------------------------------------------------------------
__global__ __launch_bounds__(512, 1)
void flash_kernel(const float* __restrict__ x,
                  const float* __restrict__ gamma,
                  float* __restrict__ out)
{
    extern __shared__ char smem[];
    const uint32_t sb = smem_u32(smem);
    float* pmax   = (float*)(smem + OFF_PMAX);   // [2][128]
    float* psum   = (float*)(smem + OFF_PSUM);   // [2][128]
    float* s_scal = (float*)(smem + OFF_SCAL);   // [128]
    float* l_row  = (float*)(smem + OFF_LROW);   // [128]

    const int b    = blockIdx.y;
    const int n0   = blockIdx.x * 128;
    const int t    = threadIdx.x;
    const int w    = t >> 5;      // 0..15
    const int lane = t & 31;
    const int gid  = lane >> 2;
    const int tig  = lane & 3;
    const int wr   = w >> 1;      // 0..7 (S rows / PV d-group)
    const int wcl  = w & 1;       // 0..1 (S cols / PV query-half)
    const int lrow = lane & 15;
    const int lk   = (lane >> 4) * 8;

    const int kr = t >> 5, kq = t & 31;   // K loads: 16 rows/pass
    const int vc = t >> 3, vu = t & 7;    // V loads: 64 ch-rows/pass

    const __half* kg_b = g_k + (size_t)b*NN*NC;
    const __half* vg_b = g_v + (size_t)b*NC*NN;

    // load Q tile (128 x 256 fp16)
    {
        const uint4* qg = (const uint4*)(g_q + (size_t)(b*NN + n0)*NC);
        #pragma unroll
        for (int it = 0; it < 8; it++) {
            int i = t + it*512;
            int r = i >> 5, gq = i & 31;
            *(uint4*)(smem + OFF_Q + r*(SQK*2) + gq*16) = qg[i];
        }
    }

    // prologue: K0 (group), V0 (group)
    {
        #pragma unroll
        for (int it = 0; it < 4; it++) {
            int r = kr + it*16;
            cp16(sb + OFF_K + r*(SQK*2) + kq*16, kg_b + (size_t)r*NC + kq*8);
        }
        CP_COMMIT();
        #pragma unroll
        for (int it = 0; it < 4; it++) {
            int c = vc + it*64;
            cp16(sb + OFF_V + c*(SVP*2) + vu*16, vg_b + (size_t)c*NN + vu*8);
        }
        CP_COMMIT();
    }

    const int r0 = 16*wr + gid;
    float m_prev[2] = {-INFINITY, -INFINITY};
    float l_acc[2]  = {0.f, 0.f};

    float o[2][8][4];
    #pragma unroll
    for (int mt = 0; mt < 2; mt++)
        #pragma unroll
        for (int nt = 0; nt < 8; nt++)
            #pragma unroll
            for (int r = 0; r < 4; r++) o[mt][nt][r] = 0.f;

    const uint32_t qa_base = sb + OFF_Q + ((16*wr + lrow)*SQK + lk)*2;
    const uint32_t ka_off  = ((32*wcl + lrow)*SQK + lk)*2;
    const uint32_t va_base = sb + OFF_V + ((32*wr + lrow)*SVP + lk)*2;
    uint32_t pa_base[4];
    #pragma unroll
    for (int jq = 0; jq < 4; jq++)
        pa_base[jq] = sb + OFF_P + ((64*wcl + 16*jq + lrow)*SVP + lk)*2;

    for (int kt = 0; kt < 64; kt++) {
        // prefetch next K into other stage
        if (kt < 63) {
            const __half* kgp = kg_b + (size_t)(kt + 1)*64*NC;
            const uint32_t kbase = sb + OFF_K + ((kt + 1) & 1)*KSTAGE;
            #pragma unroll
            for (int it = 0; it < 4; it++) {
                int r = kr + it*16;
                cp16(kbase + r*(SQK*2) + kq*16, kgp + (size_t)r*NC + kq*8);
            }
            CP_COMMIT();
            CP_WAIT(2);   // K(kt) done (pending: V(kt), K(kt+1))
        } else {
            CP_WAIT(1);   // K(63) done (pending: V(63))
        }
        __syncthreads();   // bar1: K visible

        const uint32_t ka_base = sb + OFF_K + (kt & 1)*KSTAGE + ka_off;

        // --- S = Q K^T : warp tile 16x32 ---
        float sacc[4][4];
        #pragma unroll
        for (int j = 0; j < 4; j++)
            #pragma unroll
            for (int r = 0; r < 4; r++) sacc[j][r] = 0.f;

        #pragma unroll
        for (int s = 0; s < 16; s++) {
            uint32_t a[4], b0, b1, b2, b3, c0, c1, c2, c3;
            ldsm4(a[0], a[1], a[2], a[3], qa_base + 32*s);
            ldsm4(b0, b1, b2, b3, ka_base + 32*s);
            ldsm4(c0, c1, c2, c3, ka_base + 16*(SQK*2) + 32*s);
            mma_f16(sacc[0], a, b0, b2);
            mma_f16(sacc[1], a, b1, b3);
            mma_f16(sacc[2], a, c0, c2);
            mma_f16(sacc[3], a, c1, c3);
        }

        // warp-partial row max
        {
            float mx0 = fmaxf(fmaxf(sacc[0][0], sacc[0][1]), fmaxf(sacc[1][0], sacc[1][1]));
            mx0 = fmaxf(mx0, fmaxf(fmaxf(sacc[2][0], sacc[2][1]), fmaxf(sacc[3][0], sacc[3][1])));
            float mx1 = fmaxf(fmaxf(sacc[0][2], sacc[0][3]), fmaxf(sacc[1][2], sacc[1][3]));
            mx1 = fmaxf(mx1, fmaxf(fmaxf(sacc[2][2], sacc[2][3]), fmaxf(sacc[3][2], sacc[3][3])));
            mx0 = fmaxf(mx0, __shfl_xor_sync(0xffffffffu, mx0, 1));
            mx0 = fmaxf(mx0, __shfl_xor_sync(0xffffffffu, mx0, 2));
            mx1 = fmaxf(mx1, __shfl_xor_sync(0xffffffffu, mx1, 1));
            mx1 = fmaxf(mx1, __shfl_xor_sync(0xffffffffu, mx1, 2));
            if (tig == 0) {
                pmax[wcl*128 + r0]     = mx0;
                pmax[wcl*128 + r0 + 8] = mx1;
            }
        }
        __syncthreads();   // bar2

        // --- softmax in registers ---
        float corr0, corr1;
        {
            float m_new0 = fmaxf(m_prev[0], fmaxf(pmax[r0],     pmax[128 + r0]));
            float m_new1 = fmaxf(m_prev[1], fmaxf(pmax[r0 + 8], pmax[128 + r0 + 8]));
            corr0 = __expf(m_prev[0] - m_new0);
            corr1 = __expf(m_prev[1] - m_new1);
            m_prev[0] = m_new0; m_prev[1] = m_new1;

            float ps0 = 0.f, ps1 = 0.f;
            #pragma unroll
            for (int j = 0; j < 4; j++) {
                float p0 = __expf(sacc[j][0] - m_new0);
                float p1 = __expf(sacc[j][1] - m_new0);
                float p2 = __expf(sacc[j][2] - m_new1);
                float p3 = __expf(sacc[j][3] - m_new1);
                ps0 += p0 + p1; ps1 += p2 + p3;
                int cj = 32*wcl + 8*j + 2*tig;
                *(uint32_t*)(smem + OFF_P + (r0*SVP + cj)*2)       = pack2(p0, p1);
                *(uint32_t*)(smem + OFF_P + ((r0 + 8)*SVP + cj)*2) = pack2(p2, p3);
            }
            ps0 += __shfl_xor_sync(0xffffffffu, ps0, 1);
            ps0 += __shfl_xor_sync(0xffffffffu, ps0, 2);
            ps1 += __shfl_xor_sync(0xffffffffu, ps1, 1);
            ps1 += __shfl_xor_sync(0xffffffffu, ps1, 2);
            if (tig == 0) {
                psum[wcl*128 + r0]     = ps0;
                psum[wcl*128 + r0 + 8] = ps1;
            }
            if (wcl == 0 && tig == 0) {
                s_scal[r0]     = corr0;
                s_scal[r0 + 8] = corr1;
            }
        }
        // V(kt) must be complete before PV; bar3 makes it visible block-wide
        if (kt < 63) { CP_WAIT(1); } else { CP_WAIT(0); }
        __syncthreads();   // bar3

        l_acc[0] = l_acc[0]*corr0 + psum[r0]     + psum[128 + r0];
        l_acc[1] = l_acc[1]*corr1 + psum[r0 + 8] + psum[128 + r0 + 8];

        // --- O^T = O^T*corr + V^T P^T ---
        #pragma unroll
        for (int nt = 0; nt < 8; nt++) {
            float s0 = s_scal[64*wcl + 8*nt + 2*tig];
            float s1 = s_scal[64*wcl + 8*nt + 2*tig + 1];
            #pragma unroll
            for (int mt = 0; mt < 2; mt++) {
                o[mt][nt][0] *= s0; o[mt][nt][1] *= s1;
                o[mt][nt][2] *= s0; o[mt][nt][3] *= s1;
            }
        }
        #pragma unroll
        for (int s = 0; s < 4; s++) {
            uint32_t av0[4], av1[4];
            ldsm4(av0[0], av0[1], av0[2], av0[3], va_base + 32*s);
            ldsm4(av1[0], av1[1], av1[2], av1[3], va_base + 16*(SVP*2) + 32*s);
            #pragma unroll
            for (int jq = 0; jq < 4; jq++) {
                uint32_t p0, p1, p2, p3;
                ldsm4(p0, p1, p2, p3, pa_base[jq] + 32*s);
                mma_f16(o[0][2*jq],     av0, p0, p2);
                mma_f16(o[0][2*jq + 1], av0, p1, p3);
                mma_f16(o[1][2*jq],     av1, p0, p2);
                mma_f16(o[1][2*jq + 1], av1, p1, p3);
            }
        }
        __syncthreads();   // bar4: V/P consumed

        // issue V(kt+1) into the single V buffer (overlaps next S+softmax)
        if (kt < 63) {
            const __half* vgp = vg_b + (size_t)(kt + 1)*64;
            #pragma unroll
            for (int it = 0; it < 4; it++) {
                int c = vc + it*64;
                cp16(sb + OFF_V + c*(SVP*2) + vu*16, vgp + (size_t)c*NN + vu*8);
            }
            CP_COMMIT();
        }
    }

    if (wcl == 0 && tig == 0) {
        l_row[r0]     = l_acc[0];
        l_row[r0 + 8] = l_acc[1];
    }
    __syncthreads();

    // --- O^T/l to Ot smem (channel-major) ---
    float* Ot = (float*)(smem + OFF_Q);  // 256*132*4 = 135168 <= SMEM_BYTES
    #pragma unroll
    for (int nt = 0; nt < 8; nt++) {
        int q = 64*wcl + 8*nt + 2*tig;
        float li0 = __fdividef(1.f, l_row[q]);
        float li1 = __fdividef(1.f, l_row[q + 1]);
        #pragma unroll
        for (int mt = 0; mt < 2; mt++) {
            int c = 32*wr + 16*mt + gid;
            Ot[c*SSTR2 + q]         = o[mt][nt][0] * li0;
            Ot[c*SSTR2 + q + 1]     = o[mt][nt][1] * li1;
            Ot[(c+8)*SSTR2 + q]     = o[mt][nt][2] * li0;
            Ot[(c+8)*SSTR2 + q + 1] = o[mt][nt][3] * li1;
        }
    }
    __syncthreads();

    const float g = gamma[0];
    #pragma unroll
    for (int pass = 0; pass < 2; pass++) {
        int c = pass*128 + (t >> 2);
        #pragma unroll
        for (int j = 0; j < 8; j++) {
            int f4 = (t & 3) + j*4;
            float4 ov = *(float4*)(Ot + c*SSTR2 + f4*4);
            float4 xv = *(const float4*)(x + (size_t)(b*NC + c)*NN + n0 + f4*4);
            float4 r;
            r.x = g*ov.x + xv.x; r.y = g*ov.y + xv.y;
            r.z = g*ov.z + xv.z; r.w = g*ov.w + xv.w;
            *(float4*)(out + (size_t)(b*NC + c)*NN + n0 + f4*4) = r;
        }
    }
}

// ---------------------------------------------------------------------------

extern "C" void kernel_launch(void* const* d_in, const int* in_sizes, int n_in,
                              void* d_out, int out_size)
{
    const float* x     = (const float*)d_in[0];
    const float* Wq    = (const float*)d_in[1];
    const float* Wk    = (const float*)d_in[2];
    const float* Wv    = (const float*)d_in[3];
    const float* gamma = (const float*)d_in[4];
    float* out = (float*)d_out;

    cudaFuncSetAttribute(flash_kernel,
                         cudaFuncAttributeMaxDynamicSharedMemorySize, SMEM_BYTES);
    cudaFuncSetAttribute(qkv_mma_kernel,
                         cudaFuncAttributeMaxDynamicSharedMemorySize, GEMM_SMEM);

    wconv_kernel<<<3*65536/256, 256>>>(Wq, Wk, Wv);

    dim3 gt(NN/64, NC/64, NB);
    xt_kernel<<<gt, 256>>>(x);

    dim3 gg(256, 4, 3);
    qkv_mma_kernel<<<gg, 256, GEMM_SMEM>>>();

    dim3 gf(NN/128, NB);
    flash_kernel<<<gf, 512, SMEM_BYTES>>>(x, gamma, out);
}

// round 14
// speedup vs baseline: 3.0500x; 1.0371x over previous
#include <cuda_runtime.h>
#include <cuda_fp16.h>
#include <cstdint>
#include <math.h>

#define NB 4
#define NC 256
#define NN 4096

// fp16 smem strides (elements)
#define SQK 264    // Q/K rows: 528B -> ldmatrix conflict-free
#define SVP 72     // V / P rows: 144B -> conflict-free
#define SSTR2 132  // fp32 Ot stride (128 queries + pad)

// flash smem byte offsets (BM=128; K 2-stage, V 1-stage)
#define OFF_Q    0
#define OFF_K    67584
#define KSTAGE   33792
#define OFF_V    135168
#define OFF_P    172032
#define OFF_PMAX 190464
#define OFF_LPART 191488
#define OFF_SCAL 192512
#define SMEM_BYTES 193536

// gemm smem: A tile + B tile, 64 x 264 fp16 each
#define GEMM_SMEM (2*64*SQK*2)

// scratch: q,k as (B,N,C) fp16; v as (B,C,N) fp16; xh as (B,N,C) fp16
__device__ __half g_q[NB*NN*NC];
__device__ __half g_k[NB*NN*NC];
__device__ __half g_v[NB*NN*NC];
__device__ __half g_xh[NB*NN*NC];
__device__ __half g_wh[3*NC*NC];

__device__ __forceinline__ uint32_t pack2(float a, float b) {
    __half2 h = __floats2half2_rn(a, b);
    return *(uint32_t*)&h;
}
__device__ __forceinline__ uint32_t smem_u32(const void* p) {
    uint32_t a;
    asm("{ .reg .u64 t; cvta.to.shared.u64 t, %1; cvt.u32.u64 %0, t; }" : "=r"(a) : "l"(p));
    return a;
}
__device__ __forceinline__ void ldsm4(uint32_t& r0, uint32_t& r1, uint32_t& r2,
                                      uint32_t& r3, uint32_t addr) {
    asm volatile("ldmatrix.sync.aligned.m8n8.x4.shared.b16 {%0,%1,%2,%3}, [%4];"
                 : "=r"(r0), "=r"(r1), "=r"(r2), "=r"(r3) : "r"(addr));
}
__device__ __forceinline__ void mma_f16(float* c, const uint32_t* a,
                                        uint32_t b0, uint32_t b1) {
    asm volatile(
        "mma.sync.aligned.m16n8k16.row.col.f32.f16.f16.f32 "
        "{%0,%1,%2,%3}, {%4,%5,%6,%7}, {%8,%9}, {%0,%1,%2,%3};"
        : "+f"(c[0]), "+f"(c[1]), "+f"(c[2]), "+f"(c[3])
        : "r"(a[0]), "r"(a[1]), "r"(a[2]), "r"(a[3]), "r"(b0), "r"(b1));
}
__device__ __forceinline__ void cp16(uint32_t saddr, const void* gaddr) {
    asm volatile("cp.async.cg.shared.global [%0], [%1], 16;"
                 :: "r"(saddr), "l"(gaddr));
}
#define CP_COMMIT()   asm volatile("cp.async.commit_group;" ::: "memory")
#define CP_WAIT(n)    asm volatile("cp.async.wait_group %0;" :: "n"(n) : "memory")
#define BAR_PAIR(id)  asm volatile("bar.sync %0, 64;" :: "r"(id) : "memory")

// ---------------------------------------------------------------------------
// W -> fp16 (Wq pre-scaled by log2(e) so softmax runs in base 2)
// ---------------------------------------------------------------------------
__global__ void wconv_kernel(const float* __restrict__ Wq,
                             const float* __restrict__ Wk,
                             const float* __restrict__ Wv)
{
    int i = blockIdx.x * blockDim.x + threadIdx.x;
    const float* src = (i < 65536) ? Wq : (i < 131072) ? Wk : Wv;
    int o = i & 65535;
    float v = src[o];
    if (i < 65536) v *= 1.44269504f;
    g_wh[i] = __float2half(v);
}

// ---------------------------------------------------------------------------
// x (B,C,N) fp32 -> xh (B,N,C) fp16  (64x64 tiles through smem)
// ---------------------------------------------------------------------------
__global__ __launch_bounds__(256)
void xt_kernel(const float* __restrict__ x)
{
    __shared__ float ts[64][65];
    const int n0 = blockIdx.x * 64;
    const int c0 = blockIdx.y * 64;
    const int b  = blockIdx.z;
    const int t  = threadIdx.x;

    #pragma unroll
    for (int it = 0; it < 4; it++) {
        int i = t + it*256;
        int c = i >> 4, nq = i & 15;
        float4 v = *(const float4*)&x[(size_t)(b*NC + c0 + c)*NN + n0 + nq*4];
        ts[nq*4 + 0][c] = v.x;
        ts[nq*4 + 1][c] = v.y;
        ts[nq*4 + 2][c] = v.z;
        ts[nq*4 + 3][c] = v.w;
    }
    __syncthreads();

    #pragma unroll
    for (int it = 0; it < 2; it++) {
        int i = t + it*256;
        int n = i >> 3, cq = i & 7;
        uint4 o;
        o.x = pack2(ts[n][cq*8 + 0], ts[n][cq*8 + 1]);
        o.y = pack2(ts[n][cq*8 + 2], ts[n][cq*8 + 3]);
        o.z = pack2(ts[n][cq*8 + 4], ts[n][cq*8 + 5]);
        o.w = pack2(ts[n][cq*8 + 6], ts[n][cq*8 + 7]);
        *(uint4*)&g_xh[(size_t)(b*NN + n0 + n)*NC + c0 + cq*8] = o;
    }
}

// ---------------------------------------------------------------------------
// QKV projection GEMM (fp16 mma). grid (256, 4, 3), 256 threads.
// ---------------------------------------------------------------------------
__global__ __launch_bounds__(256, 3)
void qkv_mma_kernel()
{
    extern __shared__ char smem[];
    const uint32_t sb = smem_u32(smem);
    const uint32_t SB_OFF = 64*SQK*2;

    const int bx = blockIdx.x;
    const int by = blockIdx.y;
    const int z  = blockIdx.z;

    const __half* Aptr;
    const __half* Bptr;
    if (z < 2) {
        Aptr = g_xh + (size_t)bx*64*NC;
        Bptr = g_wh + (size_t)z*65536 + (size_t)by*64*NC;
    } else {
        Aptr = g_wh + 2*65536 + (size_t)by*64*NC;
        Bptr = g_xh + (size_t)bx*64*NC;
    }

    const int t    = threadIdx.x;
    const int w    = t >> 5;
    const int lane = t & 31;
    const int gid  = lane >> 2;
    const int tig  = lane & 3;
    const int wr   = w >> 1;
    const int wcl  = w & 1;
    const int lrow = lane & 15;
    const int lk   = (lane >> 4) * 8;

    #pragma unroll
    for (int it = 0; it < 8; it++) {
        int i = t + it*256;
        int r = i >> 5, gq = i & 31;
        *(uint4*)(smem + r*(SQK*2) + gq*16) =
            ((const uint4*)(Aptr + (size_t)r*NC))[gq];
        *(uint4*)(smem + SB_OFF + r*(SQK*2) + gq*16) =
            ((const uint4*)(Bptr + (size_t)r*NC))[gq];
    }
    __syncthreads();

    float sacc[4][4];
    #pragma unroll
    for (int j = 0; j < 4; j++)
        #pragma unroll
        for (int r = 0; r < 4; r++) sacc[j][r] = 0.f;

    const uint32_t aa = sb + ((16*wr + lrow)*SQK + lk)*2;
    const uint32_t ba = sb + SB_OFF + ((32*wcl + lrow)*SQK + lk)*2;

    #pragma unroll
    for (int s = 0; s < 16; s++) {
        uint32_t a[4], b0, b1, b2, b3, c0, c1, c2, c3;
        ldsm4(a[0], a[1], a[2], a[3], aa + 32*s);
        ldsm4(b0, b1, b2, b3, ba + 32*s);
        ldsm4(c0, c1, c2, c3, ba + 16*(SQK*2) + 32*s);
        mma_f16(sacc[0], a, b0, b2);
        mma_f16(sacc[1], a, b1, b3);
        mma_f16(sacc[2], a, c0, c2);
        mma_f16(sacc[3], a, c1, c3);
    }

    #pragma unroll
    for (int mh = 0; mh < 2; mh++) {
        const int mrow = 16*wr + gid + 8*mh;
        if (z < 2) {
            __half* D = (z == 0) ? g_q : g_k;
            const size_t rb = ((size_t)bx*64 + mrow)*NC + by*64;
            #pragma unroll
            for (int j = 0; j < 4; j++)
                *(uint32_t*)&D[rb + 32*wcl + 8*j + 2*tig] =
                    pack2(sacc[j][2*mh], sacc[j][2*mh + 1]);
        } else {
            const int bb = bx >> 6;
            const int nl = (bx & 63)*64;
            const size_t rb = (size_t)bb*NC*NN + ((size_t)by*64 + mrow)*NN + nl;
            #pragma unroll
            for (int j = 0; j < 4; j++)
                *(uint32_t*)&g_v[rb + 32*wcl + 8*j + 2*tig] =
                    pack2(sacc[j][2*mh], sacc[j][2*mh + 1]);
        }
    }
}

// ---------------------------------------------------------------------------
// Fused flash attention, BM=128, BN=64, 512 threads, 1 wave.
// Named pair barriers for max exchange; lazy l reduction; base-2 softmax.
// ---------------------------------------------------------------------------
__global__ __launch_bounds__(512, 1)
void flash_kernel(const float* __restrict__ x,
                  const float* __restrict__ gamma,
                  float* __restrict__ out)
{
    extern __shared__ char smem[];
    const uint32_t sb = smem_u32(smem);
    float* pmax   = (float*)(smem + OFF_PMAX);    // [2][128]
    float* lpart  = (float*)(smem + OFF_LPART);   // [2][128]
    float* s_scal = (float*)(smem + OFF_SCAL);    // [128]

    const int b    = blockIdx.y;
    const int n0   = blockIdx.x * 128;
    const int t    = threadIdx.x;
    const int w    = t >> 5;      // 0..15
    const int lane = t & 31;
    const int gid  = lane >> 2;
    const int tig  = lane & 3;
    const int wr   = w >> 1;      // 0..7
    const int wcl  = w & 1;       // 0..1
    const int lrow = lane & 15;
    const int lk   = (lane >> 4) * 8;

    const int kr = t >> 5, kq = t & 31;
    const int vc = t >> 3, vu = t & 7;

    const __half* kg_b = g_k + (size_t)b*NN*NC;
    const __half* vg_b = g_v + (size_t)b*NC*NN;

    // load Q tile (128 x 256 fp16)
    {
        const uint4* qg = (const uint4*)(g_q + (size_t)(b*NN + n0)*NC);
        #pragma unroll
        for (int it = 0; it < 8; it++) {
            int i = t + it*512;
            int r = i >> 5, gq = i & 31;
            *(uint4*)(smem + OFF_Q + r*(SQK*2) + gq*16) = qg[i];
        }
    }

    // prologue: K0, V0
    {
        #pragma unroll
        for (int it = 0; it < 4; it++) {
            int r = kr + it*16;
            cp16(sb + OFF_K + r*(SQK*2) + kq*16, kg_b + (size_t)r*NC + kq*8);
        }
        CP_COMMIT();
        #pragma unroll
        for (int it = 0; it < 4; it++) {
            int c = vc + it*64;
            cp16(sb + OFF_V + c*(SVP*2) + vu*16, vg_b + (size_t)c*NN + vu*8);
        }
        CP_COMMIT();
    }

    const int r0 = 16*wr + gid;
    float m_prev[2] = {-INFINITY, -INFINITY};
    float l_acc[2]  = {0.f, 0.f};

    float o[2][8][4];
    #pragma unroll
    for (int mt = 0; mt < 2; mt++)
        #pragma unroll
        for (int nt = 0; nt < 8; nt++)
            #pragma unroll
            for (int r = 0; r < 4; r++) o[mt][nt][r] = 0.f;

    const uint32_t qa_base = sb + OFF_Q + ((16*wr + lrow)*SQK + lk)*2;
    const uint32_t ka_off  = ((32*wcl + lrow)*SQK + lk)*2;
    const uint32_t va_base = sb + OFF_V + ((32*wr + lrow)*SVP + lk)*2;
    uint32_t pa_base[4];
    #pragma unroll
    for (int jq = 0; jq < 4; jq++)
        pa_base[jq] = sb + OFF_P + ((64*wcl + 16*jq + lrow)*SVP + lk)*2;

    for (int kt = 0; kt < 64; kt++) {
        if (kt < 63) {
            const __half* kgp = kg_b + (size_t)(kt + 1)*64*NC;
            const uint32_t kbase = sb + OFF_K + ((kt + 1) & 1)*KSTAGE;
            #pragma unroll
            for (int it = 0; it < 4; it++) {
                int r = kr + it*16;
                cp16(kbase + r*(SQK*2) + kq*16, kgp + (size_t)r*NC + kq*8);
            }
            CP_COMMIT();
            CP_WAIT(2);   // K(kt) done
        } else {
            CP_WAIT(1);
        }
        __syncthreads();   // bar1: K visible

        const uint32_t ka_base = sb + OFF_K + (kt & 1)*KSTAGE + ka_off;

        // --- S = Q K^T (base-2 logits) ---
        float sacc[4][4];
        #pragma unroll
        for (int j = 0; j < 4; j++)
            #pragma unroll
            for (int r = 0; r < 4; r++) sacc[j][r] = 0.f;

        #pragma unroll
        for (int s = 0; s < 16; s++) {
            uint32_t a[4], b0, b1, b2, b3, c0, c1, c2, c3;
            ldsm4(a[0], a[1], a[2], a[3], qa_base + 32*s);
            ldsm4(b0, b1, b2, b3, ka_base + 32*s);
            ldsm4(c0, c1, c2, c3, ka_base + 16*(SQK*2) + 32*s);
            mma_f16(sacc[0], a, b0, b2);
            mma_f16(sacc[1], a, b1, b3);
            mma_f16(sacc[2], a, c0, c2);
            mma_f16(sacc[3], a, c1, c3);
        }

        // warp-partial row max -> pair exchange via named barrier
        {
            float mx0 = fmaxf(fmaxf(sacc[0][0], sacc[0][1]), fmaxf(sacc[1][0], sacc[1][1]));
            mx0 = fmaxf(mx0, fmaxf(fmaxf(sacc[2][0], sacc[2][1]), fmaxf(sacc[3][0], sacc[3][1])));
            float mx1 = fmaxf(fmaxf(sacc[0][2], sacc[0][3]), fmaxf(sacc[1][2], sacc[1][3]));
            mx1 = fmaxf(mx1, fmaxf(fmaxf(sacc[2][2], sacc[2][3]), fmaxf(sacc[3][2], sacc[3][3])));
            mx0 = fmaxf(mx0, __shfl_xor_sync(0xffffffffu, mx0, 1));
            mx0 = fmaxf(mx0, __shfl_xor_sync(0xffffffffu, mx0, 2));
            mx1 = fmaxf(mx1, __shfl_xor_sync(0xffffffffu, mx1, 1));
            mx1 = fmaxf(mx1, __shfl_xor_sync(0xffffffffu, mx1, 2));
            if (tig == 0) {
                pmax[wcl*128 + r0]     = mx0;
                pmax[wcl*128 + r0 + 8] = mx1;
            }
        }
        BAR_PAIR(wr + 1);   // 2-warp exchange (rows 16wr..+16)

        // --- softmax (base-2, lazy l) ---
        {
            float m_new0 = fmaxf(m_prev[0], fmaxf(pmax[r0],     pmax[128 + r0]));
            float m_new1 = fmaxf(m_prev[1], fmaxf(pmax[r0 + 8], pmax[128 + r0 + 8]));
            float corr0 = exp2f(m_prev[0] - m_new0);
            float corr1 = exp2f(m_prev[1] - m_new1);
            m_prev[0] = m_new0; m_prev[1] = m_new1;

            float ps0 = 0.f, ps1 = 0.f;
            #pragma unroll
            for (int j = 0; j < 4; j++) {
                float p0 = exp2f(sacc[j][0] - m_new0);
                float p1 = exp2f(sacc[j][1] - m_new0);
                float p2 = exp2f(sacc[j][2] - m_new1);
                float p3 = exp2f(sacc[j][3] - m_new1);
                ps0 += p0 + p1; ps1 += p2 + p3;
                int cj = 32*wcl + 8*j + 2*tig;
                *(uint32_t*)(smem + OFF_P + (r0*SVP + cj)*2)       = pack2(p0, p1);
                *(uint32_t*)(smem + OFF_P + ((r0 + 8)*SVP + cj)*2) = pack2(p2, p3);
            }
            l_acc[0] = l_acc[0]*corr0 + ps0;
            l_acc[1] = l_acc[1]*corr1 + ps1;
            if (wcl == 0 && tig == 0) {
                s_scal[r0]     = corr0;
                s_scal[r0 + 8] = corr1;
            }
        }
        // V(kt) complete before PV; bar3 publishes P + s_scal
        if (kt < 63) { CP_WAIT(1); } else { CP_WAIT(0); }
        __syncthreads();   // bar3

        // --- O^T = O^T*corr + V^T P^T (skip rescale when corr==1) ---
        {
            float sc0[8], sc1[8];
            float need = 0.f;
            #pragma unroll
            for (int nt = 0; nt < 8; nt++) {
                sc0[nt] = s_scal[64*wcl + 8*nt + 2*tig];
                sc1[nt] = s_scal[64*wcl + 8*nt + 2*tig + 1];
                need += fabsf(sc0[nt] - 1.f) + fabsf(sc1[nt] - 1.f);
            }
            if (need != 0.f) {
                #pragma unroll
                for (int nt = 0; nt < 8; nt++)
                    #pragma unroll
                    for (int mt = 0; mt < 2; mt++) {
                        o[mt][nt][0] *= sc0[nt]; o[mt][nt][1] *= sc1[nt];
                        o[mt][nt][2] *= sc0[nt]; o[mt][nt][3] *= sc1[nt];
                    }
            }
        }
        #pragma unroll
        for (int s = 0; s < 4; s++) {
            uint32_t av0[4], av1[4];
            ldsm4(av0[0], av0[1], av0[2], av0[3], va_base + 32*s);
            ldsm4(av1[0], av1[1], av1[2], av1[3], va_base + 16*(SVP*2) + 32*s);
            #pragma unroll
            for (int jq = 0; jq < 4; jq++) {
                uint32_t p0, p1, p2, p3;
                ldsm4(p0, p1, p2, p3, pa_base[jq] + 32*s);
                mma_f16(o[0][2*jq],     av0, p0, p2);
                mma_f16(o[0][2*jq + 1], av0, p1, p3);
                mma_f16(o[1][2*jq],     av1, p0, p2);
                mma_f16(o[1][2*jq + 1], av1, p1, p3);
            }
        }
        __syncthreads();   // bar4: P/V consumed

        if (kt < 63) {
            const __half* vgp = vg_b + (size_t)(kt + 1)*64;
            #pragma unroll
            for (int it = 0; it < 4; it++) {
                int c = vc + it*64;
                cp16(sb + OFF_V + c*(SVP*2) + vu*16, vgp + (size_t)c*NN + vu*8);
            }
            CP_COMMIT();
        }
    }

    // final l: reduce over tig lanes, then across wcl via smem
    {
        float l0 = l_acc[0], l1 = l_acc[1];
        l0 += __shfl_xor_sync(0xffffffffu, l0, 1);
        l0 += __shfl_xor_sync(0xffffffffu, l0, 2);
        l1 += __shfl_xor_sync(0xffffffffu, l1, 1);
        l1 += __shfl_xor_sync(0xffffffffu, l1, 2);
        if (tig == 0) {
            lpart[wcl*128 + r0]     = l0;
            lpart[wcl*128 + r0 + 8] = l1;
        }
    }
    __syncthreads();

    // --- O^T/l to Ot smem (channel-major) ---
    float* Ot = (float*)(smem + OFF_Q);
    #pragma unroll
    for (int nt = 0; nt < 8; nt++) {
        int q = 64*wcl + 8*nt + 2*tig;
        float li0 = __fdividef(1.f, lpart[q]     + lpart[128 + q]);
        float li1 = __fdividef(1.f, lpart[q + 1] + lpart[128 + q + 1]);
        #pragma unroll
        for (int mt = 0; mt < 2; mt++) {
            int c = 32*wr + 16*mt + gid;
            Ot[c*SSTR2 + q]         = o[mt][nt][0] * li0;
            Ot[c*SSTR2 + q + 1]     = o[mt][nt][1] * li1;
            Ot[(c+8)*SSTR2 + q]     = o[mt][nt][2] * li0;
            Ot[(c+8)*SSTR2 + q + 1] = o[mt][nt][3] * li1;
        }
    }
    __syncthreads();

    const float g = gamma[0];
    #pragma unroll
    for (int pass = 0; pass < 2; pass++) {
        int c = pass*128 + (t >> 2);
        #pragma unroll
        for (int j = 0; j < 8; j++) {
            int f4 = (t & 3) + j*4;
            float4 ov = *(float4*)(Ot + c*SSTR2 + f4*4);
            float4 xv = *(const float4*)(x + (size_t)(b*NC + c)*NN + n0 + f4*4);
            float4 r;
            r.x = g*ov.x + xv.x; r.y = g*ov.y + xv.y;
            r.z = g*ov.z + xv.z; r.w = g*ov.w + xv.w;
            *(float4*)(out + (size_t)(b*NC + c)*NN + n0 + f4*4) = r;
        }
    }
}

// ---------------------------------------------------------------------------

extern "C" void kernel_launch(void* const* d_in, const int* in_sizes, int n_in,
                              void* d_out, int out_size)
{
    const float* x     = (const float*)d_in[0];
    const float* Wq    = (const float*)d_in[1];
    const float* Wk    = (const float*)d_in[2];
    const float* Wv    = (const float*)d_in[3];
    const float* gamma = (const float*)d_in[4];
    float* out = (float*)d_out;

    cudaFuncSetAttribute(flash_kernel,
                         cudaFuncAttributeMaxDynamicSharedMemorySize, SMEM_BYTES);
    cudaFuncSetAttribute(qkv_mma_kernel,
                         cudaFuncAttributeMaxDynamicSharedMemorySize, GEMM_SMEM);

    wconv_kernel<<<3*65536/256, 256>>>(Wq, Wk, Wv);

    dim3 gt(NN/64, NC/64, NB);
    xt_kernel<<<gt, 256>>>(x);

    dim3 gg(256, 4, 3);
    qkv_mma_kernel<<<gg, 256, GEMM_SMEM>>>();

    dim3 gf(NN/128, NB);
    flash_kernel<<<gf, 512, SMEM_BYTES>>>(x, gamma, out);
}

// round 16
// speedup vs baseline: 3.2058x; 1.0511x over previous
#include <cuda_runtime.h>
#include <cuda_fp16.h>
#include <cstdint>
#include <math.h>

#define NB 4
#define NC 256
#define NN 4096

// fp16 smem strides (elements)
#define SQK 264    // Q/K rows: 528B -> ldmatrix conflict-free
#define SVP 72     // V / P rows: 144B -> conflict-free
#define SSTR2 132  // fp32 Ot stride (128 queries + pad)

// flash smem byte offsets (BM=128; K 2-stage, V 2-stage)
#define OFF_Q    0
#define OFF_K    67584
#define KSTAGE   33792
#define OFF_V    135168
#define VSTAGE   36864
#define OFF_P    208896
#define OFF_PMAX 227328
#define OFF_LPART 228352
#define OFF_SCAL 229376
#define SMEM_BYTES 229888

// gemm smem: A tile + B tile, 64 x 264 fp16 each
#define GEMM_SMEM (2*64*SQK*2)

// scratch: q,k as (B,N,C) fp16; v as (B,C,N) fp16; xh as (B,N,C) fp16
__device__ __half g_q[NB*NN*NC];
__device__ __half g_k[NB*NN*NC];
__device__ __half g_v[NB*NN*NC];
__device__ __half g_xh[NB*NN*NC];
__device__ __half g_wh[3*NC*NC];

__device__ __forceinline__ uint32_t pack2(float a, float b) {
    __half2 h = __floats2half2_rn(a, b);
    return *(uint32_t*)&h;
}
__device__ __forceinline__ uint32_t smem_u32(const void* p) {
    uint32_t a;
    asm("{ .reg .u64 t; cvta.to.shared.u64 t, %1; cvt.u32.u64 %0, t; }" : "=r"(a) : "l"(p));
    return a;
}
__device__ __forceinline__ void ldsm4(uint32_t& r0, uint32_t& r1, uint32_t& r2,
                                      uint32_t& r3, uint32_t addr) {
    asm volatile("ldmatrix.sync.aligned.m8n8.x4.shared.b16 {%0,%1,%2,%3}, [%4];"
                 : "=r"(r0), "=r"(r1), "=r"(r2), "=r"(r3) : "r"(addr));
}
__device__ __forceinline__ void mma_f16(float* c, const uint32_t* a,
                                        uint32_t b0, uint32_t b1) {
    asm volatile(
        "mma.sync.aligned.m16n8k16.row.col.f32.f16.f16.f32 "
        "{%0,%1,%2,%3}, {%4,%5,%6,%7}, {%8,%9}, {%0,%1,%2,%3};"
        : "+f"(c[0]), "+f"(c[1]), "+f"(c[2]), "+f"(c[3])
        : "r"(a[0]), "r"(a[1]), "r"(a[2]), "r"(a[3]), "r"(b0), "r"(b1));
}
__device__ __forceinline__ void cp16(uint32_t saddr, const void* gaddr) {
    asm volatile("cp.async.cg.shared.global [%0], [%1], 16;"
                 :: "r"(saddr), "l"(gaddr));
}
#define CP_COMMIT()   asm volatile("cp.async.commit_group;" ::: "memory")
#define CP_WAIT(n)    asm volatile("cp.async.wait_group %0;" :: "n"(n) : "memory")
#define BAR_PAIR(id)  asm volatile("bar.sync %0, 64;" :: "r"(id) : "memory")

// ---------------------------------------------------------------------------
// W -> fp16 (Wq pre-scaled by log2(e) so softmax runs in base 2)
// ---------------------------------------------------------------------------
__global__ void wconv_kernel(const float* __restrict__ Wq,
                             const float* __restrict__ Wk,
                             const float* __restrict__ Wv)
{
    int i = blockIdx.x * blockDim.x + threadIdx.x;
    const float* src = (i < 65536) ? Wq : (i < 131072) ? Wk : Wv;
    int o = i & 65535;
    float v = src[o];
    if (i < 65536) v *= 1.44269504f;
    g_wh[i] = __float2half(v);
}

// ---------------------------------------------------------------------------
// x (B,C,N) fp32 -> xh (B,N,C) fp16  (64x64 tiles through smem)
// ---------------------------------------------------------------------------
__global__ __launch_bounds__(256)
void xt_kernel(const float* __restrict__ x)
{
    __shared__ float ts[64][65];
    const int n0 = blockIdx.x * 64;
    const int c0 = blockIdx.y * 64;
    const int b  = blockIdx.z;
    const int t  = threadIdx.x;

    #pragma unroll
    for (int it = 0; it < 4; it++) {
        int i = t + it*256;
        int c = i >> 4, nq = i & 15;
        float4 v = *(const float4*)&x[(size_t)(b*NC + c0 + c)*NN + n0 + nq*4];
        ts[nq*4 + 0][c] = v.x;
        ts[nq*4 + 1][c] = v.y;
        ts[nq*4 + 2][c] = v.z;
        ts[nq*4 + 3][c] = v.w;
    }
    __syncthreads();

    #pragma unroll
    for (int it = 0; it < 2; it++) {
        int i = t + it*256;
        int n = i >> 3, cq = i & 7;
        uint4 o;
        o.x = pack2(ts[n][cq*8 + 0], ts[n][cq*8 + 1]);
        o.y = pack2(ts[n][cq*8 + 2], ts[n][cq*8 + 3]);
        o.z = pack2(ts[n][cq*8 + 4], ts[n][cq*8 + 5]);
        o.w = pack2(ts[n][cq*8 + 6], ts[n][cq*8 + 7]);
        *(uint4*)&g_xh[(size_t)(b*NN + n0 + n)*NC + c0 + cq*8] = o;
    }
}

// ---------------------------------------------------------------------------
// QKV projection GEMM (fp16 mma). grid (256, 4, 3), 256 threads.
// ---------------------------------------------------------------------------
__global__ __launch_bounds__(256, 3)
void qkv_mma_kernel()
{
    extern __shared__ char smem[];
    const uint32_t sb = smem_u32(smem);
    const uint32_t SB_OFF = 64*SQK*2;

    const int bx = blockIdx.x;
    const int by = blockIdx.y;
    const int z  = blockIdx.z;

    const __half* Aptr;
    const __half* Bptr;
    if (z < 2) {
        Aptr = g_xh + (size_t)bx*64*NC;
        Bptr = g_wh + (size_t)z*65536 + (size_t)by*64*NC;
    } else {
        Aptr = g_wh + 2*65536 + (size_t)by*64*NC;
        Bptr = g_xh + (size_t)bx*64*NC;
    }

    const int t    = threadIdx.x;
    const int w    = t >> 5;
    const int lane = t & 31;
    const int gid  = lane >> 2;
    const int tig  = lane & 3;
    const int wr   = w >> 1;
    const int wcl  = w & 1;
    const int lrow = lane & 15;
    const int lk   = (lane >> 4) * 8;

    #pragma unroll
    for (int it = 0; it < 8; it++) {
        int i = t + it*256;
        int r = i >> 5, gq = i & 31;
        *(uint4*)(smem + r*(SQK*2) + gq*16) =
            ((const uint4*)(Aptr + (size_t)r*NC))[gq];
        *(uint4*)(smem + SB_OFF + r*(SQK*2) + gq*16) =
            ((const uint4*)(Bptr + (size_t)r*NC))[gq];
    }
    __syncthreads();

    float sacc[4][4];
    #pragma unroll
    for (int j = 0; j < 4; j++)
        #pragma unroll
        for (int r = 0; r < 4; r++) sacc[j][r] = 0.f;

    const uint32_t aa = sb + ((16*wr + lrow)*SQK + lk)*2;
    const uint32_t ba = sb + SB_OFF + ((32*wcl + lrow)*SQK + lk)*2;

    #pragma unroll
    for (int s = 0; s < 16; s++) {
        uint32_t a[4], b0, b1, b2, b3, c0, c1, c2, c3;
        ldsm4(a[0], a[1], a[2], a[3], aa + 32*s);
        ldsm4(b0, b1, b2, b3, ba + 32*s);
        ldsm4(c0, c1, c2, c3, ba + 16*(SQK*2) + 32*s);
        mma_f16(sacc[0], a, b0, b2);
        mma_f16(sacc[1], a, b1, b3);
        mma_f16(sacc[2], a, c0, c2);
        mma_f16(sacc[3], a, c1, c3);
    }

    #pragma unroll
    for (int mh = 0; mh < 2; mh++) {
        const int mrow = 16*wr + gid + 8*mh;
        if (z < 2) {
            __half* D = (z == 0) ? g_q : g_k;
            const size_t rb = ((size_t)bx*64 + mrow)*NC + by*64;
            #pragma unroll
            for (int j = 0; j < 4; j++)
                *(uint32_t*)&D[rb + 32*wcl + 8*j + 2*tig] =
                    pack2(sacc[j][2*mh], sacc[j][2*mh + 1]);
        } else {
            const int bb = bx >> 6;
            const int nl = (bx & 63)*64;
            const size_t rb = (size_t)bb*NC*NN + ((size_t)by*64 + mrow)*NN + nl;
            #pragma unroll
            for (int j = 0; j < 4; j++)
                *(uint32_t*)&g_v[rb + 32*wcl + 8*j + 2*tig] =
                    pack2(sacc[j][2*mh], sacc[j][2*mh + 1]);
        }
    }
}

// ---------------------------------------------------------------------------
// Fused flash attention, BM=128, BN=64, 512 threads, 1 wave.
// K + V both 2-stage cp.async; 2 block barriers + 1 pair barrier per iter.
// ---------------------------------------------------------------------------
__global__ __launch_bounds__(512, 1)
void flash_kernel(const float* __restrict__ x,
                  const float* __restrict__ gamma,
                  float* __restrict__ out)
{
    extern __shared__ char smem[];
    const uint32_t sb = smem_u32(smem);
    float* pmax   = (float*)(smem + OFF_PMAX);    // [2][128]
    float* lpart  = (float*)(smem + OFF_LPART);   // [2][128]
    float* s_scal = (float*)(smem + OFF_SCAL);    // [128]

    const int b    = blockIdx.y;
    const int n0   = blockIdx.x * 128;
    const int t    = threadIdx.x;
    const int w    = t >> 5;      // 0..15
    const int lane = t & 31;
    const int gid  = lane >> 2;
    const int tig  = lane & 3;
    const int wr   = w >> 1;      // 0..7
    const int wcl  = w & 1;       // 0..1
    const int lrow = lane & 15;
    const int lk   = (lane >> 4) * 8;

    const int kr = t >> 5, kq = t & 31;
    const int vc = t >> 3, vu = t & 7;

    const __half* kg_b = g_k + (size_t)b*NN*NC;
    const __half* vg_b = g_v + (size_t)b*NC*NN;

    // load Q tile (128 x 256 fp16)
    {
        const uint4* qg = (const uint4*)(g_q + (size_t)(b*NN + n0)*NC);
        #pragma unroll
        for (int it = 0; it < 8; it++) {
            int i = t + it*512;
            int r = i >> 5, gq = i & 31;
            *(uint4*)(smem + OFF_Q + r*(SQK*2) + gq*16) = qg[i];
        }
    }

    // prologue: K0 (group), V0 (group) into stage 0
    {
        #pragma unroll
        for (int it = 0; it < 4; it++) {
            int r = kr + it*16;
            cp16(sb + OFF_K + r*(SQK*2) + kq*16, kg_b + (size_t)r*NC + kq*8);
        }
        CP_COMMIT();
        #pragma unroll
        for (int it = 0; it < 4; it++) {
            int c = vc + it*64;
            cp16(sb + OFF_V + c*(SVP*2) + vu*16, vg_b + (size_t)c*NN + vu*8);
        }
        CP_COMMIT();
    }

    const int r0 = 16*wr + gid;
    float m_prev[2] = {-INFINITY, -INFINITY};
    float l_acc[2]  = {0.f, 0.f};

    float o[2][8][4];
    #pragma unroll
    for (int mt = 0; mt < 2; mt++)
        #pragma unroll
        for (int nt = 0; nt < 8; nt++)
            #pragma unroll
            for (int r = 0; r < 4; r++) o[mt][nt][r] = 0.f;

    const uint32_t qa_base = sb + OFF_Q + ((16*wr + lrow)*SQK + lk)*2;
    const uint32_t ka_off  = ((32*wcl + lrow)*SQK + lk)*2;
    const uint32_t va_off  = ((32*wr + lrow)*SVP + lk)*2;
    uint32_t pa_base[4];
    #pragma unroll
    for (int jq = 0; jq < 4; jq++)
        pa_base[jq] = sb + OFF_P + ((64*wcl + 16*jq + lrow)*SVP + lk)*2;

    for (int kt = 0; kt < 64; kt++) {
        // commit K(t+1), then wait for K(t) [pending allowed: V(t), K(t+1)]
        if (kt < 63) {
            const __half* kgp = kg_b + (size_t)(kt + 1)*64*NC;
            const uint32_t kbase = sb + OFF_K + ((kt + 1) & 1)*KSTAGE;
            #pragma unroll
            for (int it = 0; it < 4; it++) {
                int r = kr + it*16;
                cp16(kbase + r*(SQK*2) + kq*16, kgp + (size_t)r*NC + kq*8);
            }
            CP_COMMIT();
            CP_WAIT(2);
        } else {
            CP_WAIT(1);
        }
        __syncthreads();   // bar1: K(t) visible; PV(t-1) globally complete

        // issue V(t+1) into other stage (safe: after bar1; overlaps S+softmax+PV)
        if (kt < 63) {
            const __half* vgp = vg_b + (size_t)(kt + 1)*64;
            const uint32_t vbase = sb + OFF_V + ((kt + 1) & 1)*VSTAGE;
            #pragma unroll
            for (int it = 0; it < 4; it++) {
                int c = vc + it*64;
                cp16(vbase + c*(SVP*2) + vu*16, vgp + (size_t)c*NN + vu*8);
            }
            CP_COMMIT();
        }

        const uint32_t ka_base = sb + OFF_K + (kt & 1)*KSTAGE + ka_off;
        const uint32_t va_base = sb + OFF_V + (kt & 1)*VSTAGE + va_off;

        // --- S = Q K^T (base-2 logits) ---
        float sacc[4][4];
        #pragma unroll
        for (int j = 0; j < 4; j++)
            #pragma unroll
            for (int r = 0; r < 4; r++) sacc[j][r] = 0.f;

        #pragma unroll
        for (int s = 0; s < 16; s++) {
            uint32_t a[4], b0, b1, b2, b3, c0, c1, c2, c3;
            ldsm4(a[0], a[1], a[2], a[3], qa_base + 32*s);
            ldsm4(b0, b1, b2, b3, ka_base + 32*s);
            ldsm4(c0, c1, c2, c3, ka_base + 16*(SQK*2) + 32*s);
            mma_f16(sacc[0], a, b0, b2);
            mma_f16(sacc[1], a, b1, b3);
            mma_f16(sacc[2], a, c0, c2);
            mma_f16(sacc[3], a, c1, c3);
        }

        // warp-partial row max -> pair exchange via named barrier
        {
            float mx0 = fmaxf(fmaxf(sacc[0][0], sacc[0][1]), fmaxf(sacc[1][0], sacc[1][1]));
            mx0 = fmaxf(mx0, fmaxf(fmaxf(sacc[2][0], sacc[2][1]), fmaxf(sacc[3][0], sacc[3][1])));
            float mx1 = fmaxf(fmaxf(sacc[0][2], sacc[0][3]), fmaxf(sacc[1][2], sacc[1][3]));
            mx1 = fmaxf(mx1, fmaxf(fmaxf(sacc[2][2], sacc[2][3]), fmaxf(sacc[3][2], sacc[3][3])));
            mx0 = fmaxf(mx0, __shfl_xor_sync(0xffffffffu, mx0, 1));
            mx0 = fmaxf(mx0, __shfl_xor_sync(0xffffffffu, mx0, 2));
            mx1 = fmaxf(mx1, __shfl_xor_sync(0xffffffffu, mx1, 1));
            mx1 = fmaxf(mx1, __shfl_xor_sync(0xffffffffu, mx1, 2));
            if (tig == 0) {
                pmax[wcl*128 + r0]     = mx0;
                pmax[wcl*128 + r0 + 8] = mx1;
            }
        }
        BAR_PAIR(wr + 1);   // 2-warp exchange (rows 16wr..+16)

        // --- softmax (base-2, lazy l) ---
        {
            float m_new0 = fmaxf(m_prev[0], fmaxf(pmax[r0],     pmax[128 + r0]));
            float m_new1 = fmaxf(m_prev[1], fmaxf(pmax[r0 + 8], pmax[128 + r0 + 8]));
            float corr0 = exp2f(m_prev[0] - m_new0);
            float corr1 = exp2f(m_prev[1] - m_new1);
            m_prev[0] = m_new0; m_prev[1] = m_new1;

            float ps0 = 0.f, ps1 = 0.f;
            #pragma unroll
            for (int j = 0; j < 4; j++) {
                float p0 = exp2f(sacc[j][0] - m_new0);
                float p1 = exp2f(sacc[j][1] - m_new0);
                float p2 = exp2f(sacc[j][2] - m_new1);
                float p3 = exp2f(sacc[j][3] - m_new1);
                ps0 += p0 + p1; ps1 += p2 + p3;
                int cj = 32*wcl + 8*j + 2*tig;
                *(uint32_t*)(smem + OFF_P + (r0*SVP + cj)*2)       = pack2(p0, p1);
                *(uint32_t*)(smem + OFF_P + ((r0 + 8)*SVP + cj)*2) = pack2(p2, p3);
            }
            l_acc[0] = l_acc[0]*corr0 + ps0;
            l_acc[1] = l_acc[1]*corr1 + ps1;
            if (wcl == 0 && tig == 0) {
                s_scal[r0]     = corr0;
                s_scal[r0 + 8] = corr1;
            }
        }
        // V(t) complete [pending allowed: K(t+1), V(t+1)]; bar3 publishes P/V/s_scal
        if (kt < 63) { CP_WAIT(2); } else { CP_WAIT(0); }
        __syncthreads();   // bar3

        // --- O^T = O^T*corr + V^T P^T (skip rescale when corr==1) ---
        {
            float sc0[8], sc1[8];
            float need = 0.f;
            #pragma unroll
            for (int nt = 0; nt < 8; nt++) {
                sc0[nt] = s_scal[64*wcl + 8*nt + 2*tig];
                sc1[nt] = s_scal[64*wcl + 8*nt + 2*tig + 1];
                need += fabsf(sc0[nt] - 1.f) + fabsf(sc1[nt] - 1.f);
            }
            if (need != 0.f) {
                #pragma unroll
                for (int nt = 0; nt < 8; nt++)
                    #pragma unroll
                    for (int mt = 0; mt < 2; mt++) {
                        o[mt][nt][0] *= sc0[nt]; o[mt][nt][1] *= sc1[nt];
                        o[mt][nt][2] *= sc0[nt]; o[mt][nt][3] *= sc1[nt];
                    }
            }
        }
        #pragma unroll
        for (int s = 0; s < 4; s++) {
            uint32_t av0[4], av1[4];
            ldsm4(av0[0], av0[1], av0[2], av0[3], va_base + 32*s);
            ldsm4(av1[0], av1[1], av1[2], av1[3], va_base + 16*(SVP*2) + 32*s);
            #pragma unroll
            for (int jq = 0; jq < 4; jq++) {
                uint32_t p0, p1, p2, p3;
                ldsm4(p0, p1, p2, p3, pa_base[jq] + 32*s);
                mma_f16(o[0][2*jq],     av0, p0, p2);
                mma_f16(o[0][2*jq + 1], av0, p1, p3);
                mma_f16(o[1][2*jq],     av1, p0, p2);
                mma_f16(o[1][2*jq + 1], av1, p1, p3);
            }
        }
        // no bar4: P/V reuse hazards fenced by bar1 of next iteration
    }

    // final l: reduce over tig lanes, then across wcl via smem
    {
        float l0 = l_acc[0], l1 = l_acc[1];
        l0 += __shfl_xor_sync(0xffffffffu, l0, 1);
        l0 += __shfl_xor_sync(0xffffffffu, l0, 2);
        l1 += __shfl_xor_sync(0xffffffffu, l1, 1);
        l1 += __shfl_xor_sync(0xffffffffu, l1, 2);
        if (tig == 0) {
            lpart[wcl*128 + r0]     = l0;
            lpart[wcl*128 + r0 + 8] = l1;
        }
    }
    __syncthreads();

    // --- O^T/l to Ot smem (channel-major) ---
    float* Ot = (float*)(smem + OFF_Q);
    #pragma unroll
    for (int nt = 0; nt < 8; nt++) {
        int q = 64*wcl + 8*nt + 2*tig;
        float li0 = __fdividef(1.f, lpart[q]     + lpart[128 + q]);
        float li1 = __fdividef(1.f, lpart[q + 1] + lpart[128 + q + 1]);
        #pragma unroll
        for (int mt = 0; mt < 2; mt++) {
            int c = 32*wr + 16*mt + gid;
            Ot[c*SSTR2 + q]         = o[mt][nt][0] * li0;
            Ot[c*SSTR2 + q + 1]     = o[mt][nt][1] * li1;
            Ot[(c+8)*SSTR2 + q]     = o[mt][nt][2] * li0;
            Ot[(c+8)*SSTR2 + q + 1] = o[mt][nt][3] * li1;
        }
    }
    __syncthreads();

    const float g = gamma[0];
    #pragma unroll
    for (int pass = 0; pass < 2; pass++) {
        int c = pass*128 + (t >> 2);
        #pragma unroll
        for (int j = 0; j < 8; j++) {
            int f4 = (t & 3) + j*4;
            float4 ov = *(float4*)(Ot + c*SSTR2 + f4*4);
            float4 xv = *(const float4*)(x + (size_t)(b*NC + c)*NN + n0 + f4*4);
            float4 r;
            r.x = g*ov.x + xv.x; r.y = g*ov.y + xv.y;
            r.z = g*ov.z + xv.z; r.w = g*ov.w + xv.w;
            *(float4*)(out + (size_t)(b*NC + c)*NN + n0 + f4*4) = r;
        }
    }
}

// ---------------------------------------------------------------------------

extern "C" void kernel_launch(void* const* d_in, const int* in_sizes, int n_in,
                              void* d_out, int out_size)
{
    const float* x     = (const float*)d_in[0];
    const float* Wq    = (const float*)d_in[1];
    const float* Wk    = (const float*)d_in[2];
    const float* Wv    = (const float*)d_in[3];
    const float* gamma = (const float*)d_in[4];
    float* out = (float*)d_out;

    cudaFuncSetAttribute(flash_kernel,
                         cudaFuncAttributeMaxDynamicSharedMemorySize, SMEM_BYTES);
    cudaFuncSetAttribute(qkv_mma_kernel,
                         cudaFuncAttributeMaxDynamicSharedMemorySize, GEMM_SMEM);

    wconv_kernel<<<3*65536/256, 256>>>(Wq, Wk, Wv);

    dim3 gt(NN/64, NC/64, NB);
    xt_kernel<<<gt, 256>>>(x);

    dim3 gg(256, 4, 3);
    qkv_mma_kernel<<<gg, 256, GEMM_SMEM>>>();

    dim3 gf(NN/128, NB);
    flash_kernel<<<gf, 512, SMEM_BYTES>>>(x, gamma, out);
}